// round 11
// baseline (speedup 1.0000x reference)
#include <cuda_runtime.h>
#include <cuda_bf16.h>
#include <stdint.h>

// Problem constants
#define B_ 8
#define N_ 512
#define D_ 768
#define A_ 12
#define E_ 64
#define M_ (B_ * N_)   // 4096

// ---------------------------------------------------------------------------
// PTX helpers (all baseline features: valid for compute_103 virtual arch)
// ---------------------------------------------------------------------------
__device__ __forceinline__ uint32_t smem_u32(const void* p) {
    uint32_t a;
    asm("{ .reg .u64 t; cvta.to.shared.u64 t, %1; cvt.u32.u64 %0, t; }" : "=r"(a) : "l"(p));
    return a;
}
__device__ __forceinline__ void ldsm_x4(uint32_t* r, uint32_t addr) {
    asm volatile("ldmatrix.sync.aligned.m8n8.x4.shared.b16 {%0,%1,%2,%3}, [%4];"
        : "=r"(r[0]), "=r"(r[1]), "=r"(r[2]), "=r"(r[3]) : "r"(addr));
}
__device__ __forceinline__ void ldsm_x4_t(uint32_t* r, uint32_t addr) {
    asm volatile("ldmatrix.sync.aligned.m8n8.x4.trans.shared.b16 {%0,%1,%2,%3}, [%4];"
        : "=r"(r[0]), "=r"(r[1]), "=r"(r[2]), "=r"(r[3]) : "r"(addr));
}
#define CP16(dst, src) asm volatile("cp.async.cg.shared.global [%0], [%1], 16;" :: "r"(dst), "l"(src))
#define CP_COMMIT() asm volatile("cp.async.commit_group;" ::: "memory")
#define CP_WAIT1() asm volatile("cp.async.wait_group 1;" ::: "memory")
#define CP_WAIT0() asm volatile("cp.async.wait_group 0;" ::: "memory")

__device__ __forceinline__ void mma16816(float* c,
        uint32_t a0, uint32_t a1, uint32_t a2, uint32_t a3,
        uint32_t b0, uint32_t b1) {
    asm volatile(
        "mma.sync.aligned.m16n8k16.row.col.f32.bf16.bf16.f32 "
        "{%0,%1,%2,%3}, {%4,%5,%6,%7}, {%8,%9}, {%0,%1,%2,%3};"
        : "+f"(c[0]), "+f"(c[1]), "+f"(c[2]), "+f"(c[3])
        : "r"(a0), "r"(a1), "r"(a2), "r"(a3), "r"(b0), "r"(b1));
}

// ---------------------------------------------------------------------------
// Scratch (device globals: allocation-free)
// ---------------------------------------------------------------------------
__device__ float g_src[B_ * A_ * N_];
__device__ float g_dst[B_ * A_ * N_];
__device__ float g_att[B_ * N_ * D_];        // [b][i][a*64+e]
__device__ int   g_adj_int;
// h in bf16 hi/lo, layout [ba][j][e] (j = node, e = head dim)
__device__ __align__(16) __nv_bfloat16 g_hbh[B_ * A_ * N_ * E_];
__device__ __align__(16) __nv_bfloat16 g_hbl[B_ * A_ * N_ * E_];
// bf16 split GEMM operands (hi + lo)
__device__ __align__(16) __nv_bfloat16 g_fh[M_ * D_];
__device__ __align__(16) __nv_bfloat16 g_fl[M_ * D_];
__device__ __align__(16) __nv_bfloat16 g_w1h[D_ * D_];  // W^T: row n=a*64+e, col k=d
__device__ __align__(16) __nv_bfloat16 g_w1l[D_ * D_];
__device__ __align__(16) __nv_bfloat16 g_w2h[D_ * D_];  // Hw: row n, col k=d
__device__ __align__(16) __nv_bfloat16 g_w2l[D_ * D_];

// ---------------------------------------------------------------------------
// adj dtype detection
// ---------------------------------------------------------------------------
__global__ void detect_adj_kernel(const int* __restrict__ adj) {
    int ok = 1;
    for (int v = threadIdx.x; v < 1024; v += 32) {
        int w = adj[v];
        if (w != 0 && w != 1) ok = 0;
    }
#pragma unroll
    for (int o = 16; o; o >>= 1) ok &= __shfl_xor_sync(0xffffffffu, ok, o);
    if (threadIdx.x == 0) g_adj_int = ok;
}

// ---------------------------------------------------------------------------
// fp32 -> bf16 hi/lo split conversions
// ---------------------------------------------------------------------------
__device__ __forceinline__ void split2(float x, __nv_bfloat16& h, __nv_bfloat16& l) {
    h = __float2bfloat16(x);
    l = __float2bfloat16(x - __bfloat162float(h));
}

__global__ void conv_feat_kernel(const float* __restrict__ f) {
    const int g4 = (blockIdx.x * 256 + threadIdx.x) * 4;
    float4 v = *(const float4*)(f + g4);
    __nv_bfloat16 h0, h1, h2, h3, l0, l1, l2, l3;
    split2(v.x, h0, l0); split2(v.y, h1, l1); split2(v.z, h2, l2); split2(v.w, h3, l3);
    ((__nv_bfloat162*)(g_fh + g4))[0] = __nv_bfloat162(h0, h1);
    ((__nv_bfloat162*)(g_fh + g4))[1] = __nv_bfloat162(h2, h3);
    ((__nv_bfloat162*)(g_fl + g4))[0] = __nv_bfloat162(l0, l1);
    ((__nv_bfloat162*)(g_fl + g4))[1] = __nv_bfloat162(l2, l3);
}

// W [a][d][e] -> W^T rows n=a*64+e, cols d; smem-transpose for coalescing.
__global__ void conv_w1_kernel(const float* __restrict__ W) {
    __shared__ float tile[64][65];
    const int a = blockIdx.x, d0 = blockIdx.y * 64;
    const int tid = threadIdx.x;
#pragma unroll
    for (int it = 0; it < 16; ++it) {
        const int idx = it * 256 + tid;
        const int dd = idx >> 6, e = idx & 63;
        tile[dd][e] = W[(a * D_ + d0 + dd) * E_ + e];
    }
    __syncthreads();
#pragma unroll
    for (int it = 0; it < 16; ++it) {
        const int idx = it * 256 + tid;
        const int e = idx >> 6, dd = idx & 63;
        __nv_bfloat16 h, l;
        split2(tile[dd][e], h, l);
        g_w1h[(a * 64 + e) * D_ + d0 + dd] = h;
        g_w1l[(a * 64 + e) * D_ + d0 + dd] = l;
    }
}

__global__ void conv_w2_kernel(const float* __restrict__ Hw) {
    const int g4 = (blockIdx.x * 256 + threadIdx.x) * 4;
    float4 v = *(const float4*)(Hw + g4);
    __nv_bfloat16 h0, h1, h2, h3, l0, l1, l2, l3;
    split2(v.x, h0, l0); split2(v.y, h1, l1); split2(v.z, h2, l2); split2(v.w, h3, l3);
    ((__nv_bfloat162*)(g_w2h + g4))[0] = __nv_bfloat162(h0, h1);
    ((__nv_bfloat162*)(g_w2h + g4))[1] = __nv_bfloat162(h2, h3);
    ((__nv_bfloat162*)(g_w2l + g4))[0] = __nv_bfloat162(l0, l1);
    ((__nv_bfloat162*)(g_w2l + g4))[1] = __nv_bfloat162(l2, l3);
}

// ---------------------------------------------------------------------------
// HMMA bf16x3 GEMM: 128x128 block, 8 warps (4m x 2n), warp 32x64.
// ---------------------------------------------------------------------------
#define KC_ 32
#define NKC_ (D_ / KC_)          // 24
#define TROW_B 80
#define TILE_B (128 * TROW_B)    // 10240
#define BUF_B (4 * TILE_B)       // 40960
#define GEMM_SMEM (2 * BUF_B)    // 81920

__device__ __forceinline__ void hmma_mainloop(
        float acc[2][8][4],
        const __nv_bfloat16* __restrict__ Ah, const __nv_bfloat16* __restrict__ Al,
        const __nv_bfloat16* __restrict__ Bh, const __nv_bfloat16* __restrict__ Bl,
        int m0, int n0, char* sm) {
    const int tid = threadIdx.x;
    const int warp = tid >> 5, lane = tid & 31;
    const int wm = warp & 3, wn = warp >> 2;

    const int lr = tid >> 1;
    const int lce = (tid & 1) * 16;
    const uint32_t sto = (uint32_t)lr * TROW_B + (tid & 1) * 32;
    const uint32_t smu = smem_u32(sm);

    const __nv_bfloat16* pAh = Ah + (size_t)(m0 + lr) * D_ + lce;
    const __nv_bfloat16* pAl = Al + (size_t)(m0 + lr) * D_ + lce;
    const __nv_bfloat16* pBh = Bh + (size_t)(n0 + lr) * D_ + lce;
    const __nv_bfloat16* pBl = Bl + (size_t)(n0 + lr) * D_ + lce;

#define ISSUE(kc, buf) do {                                                  \
    uint32_t _bb = smu + (buf) * BUF_B + sto;                                \
    const int _o = (kc) * KC_;                                               \
    CP16(_bb, pAh + _o);                 CP16(_bb + 16, pAh + _o + 8);       \
    CP16(_bb + TILE_B, pAl + _o);        CP16(_bb + TILE_B + 16, pAl + _o + 8); \
    CP16(_bb + 2 * TILE_B, pBh + _o);    CP16(_bb + 2 * TILE_B + 16, pBh + _o + 8); \
    CP16(_bb + 3 * TILE_B, pBl + _o);    CP16(_bb + 3 * TILE_B + 16, pBl + _o + 8); \
    CP_COMMIT(); } while (0)

    ISSUE(0, 0);

    const int arow = (lane & 7) + ((lane >> 3) & 1) * 8;
    const int acolb = (lane >> 4) * 16;
    const int brow = (lane & 7) + (lane >> 4) * 8;
    const int bcolb = ((lane >> 3) & 1) * 16;

    for (int kc = 0; kc < NKC_; ++kc) {
        if (kc + 1 < NKC_) { ISSUE(kc + 1, (kc + 1) & 1); CP_WAIT1(); }
        else               { CP_WAIT0(); }
        __syncthreads();
        const uint32_t bufb = smu + (kc & 1) * BUF_B;
        const uint32_t aA0 = bufb + (uint32_t)(wm * 32 + arow) * TROW_B + acolb;
        const uint32_t bB0 = bufb + 2 * TILE_B + (uint32_t)(wn * 64 + brow) * TROW_B + bcolb;
#pragma unroll
        for (int ks = 0; ks < 2; ++ks) {
            uint32_t ah[2][4], al[2][4], bh[4][4], bl[4][4];
#pragma unroll
            for (int mf = 0; mf < 2; ++mf) {
                ldsm_x4(ah[mf], aA0 + mf * 16 * TROW_B + ks * 32);
                ldsm_x4(al[mf], aA0 + TILE_B + mf * 16 * TROW_B + ks * 32);
            }
#pragma unroll
            for (int nfp = 0; nfp < 4; ++nfp) {
                ldsm_x4(bh[nfp], bB0 + nfp * 16 * TROW_B + ks * 32);
                ldsm_x4(bl[nfp], bB0 + TILE_B + nfp * 16 * TROW_B + ks * 32);
            }
#pragma unroll
            for (int nfp = 0; nfp < 4; ++nfp)
#pragma unroll
                for (int hf = 0; hf < 2; ++hf) {
                    const int nf = nfp * 2 + hf;
                    const uint32_t b0h = bh[nfp][hf * 2], b1h = bh[nfp][hf * 2 + 1];
                    const uint32_t b0l = bl[nfp][hf * 2], b1l = bl[nfp][hf * 2 + 1];
#pragma unroll
                    for (int mf = 0; mf < 2; ++mf) {
                        mma16816(acc[mf][nf], ah[mf][0], ah[mf][1], ah[mf][2], ah[mf][3], b0h, b1h);
                        mma16816(acc[mf][nf], al[mf][0], al[mf][1], al[mf][2], al[mf][3], b0h, b1h);
                        mma16816(acc[mf][nf], ah[mf][0], ah[mf][1], ah[mf][2], ah[mf][3], b0l, b1l);
                    }
                }
        }
        __syncthreads();
    }
#undef ISSUE
}

// ---------------------------------------------------------------------------
// GEMM-1 (HMMA): h = feat @ W^T; epilogue splits h + fused src/dst logits.
// ---------------------------------------------------------------------------
__global__ __launch_bounds__(256) void gemm1_tc_kernel(const float* __restrict__ wsrc,
                                                       const float* __restrict__ wdst) {
    extern __shared__ char sm[];
    const int m0 = blockIdx.y << 7;
    const int n0 = blockIdx.x << 7;
    float acc[2][8][4];
#pragma unroll
    for (int mf = 0; mf < 2; ++mf)
#pragma unroll
        for (int nf = 0; nf < 8; ++nf)
#pragma unroll
            for (int q = 0; q < 4; ++q) acc[mf][nf][q] = 0.f;

    hmma_mainloop(acc, g_fh, g_fl, g_w1h, g_w1l, m0, n0, sm);

    const int warp = threadIdx.x >> 5, lane = threadIdx.x & 31;
    const int wm = warp & 3, wn = warp >> 2;
    const int g = lane >> 2, t = lane & 3;
    const int head = (n0 >> 6) + wn;

    float sd[2][2], dd[2][2];
#pragma unroll
    for (int mf = 0; mf < 2; ++mf) sd[mf][0] = sd[mf][1] = dd[mf][0] = dd[mf][1] = 0.f;

#pragma unroll
    for (int mf = 0; mf < 2; ++mf) {
        const int m = m0 + wm * 32 + mf * 16 + g;
        const int b = m >> 9, i = m & (N_ - 1);
        const int ba = b * A_ + head;
#pragma unroll
        for (int nf = 0; nf < 8; ++nf) {
            const int e = nf * 8 + 2 * t;
            __nv_bfloat16 h0, l0, h1, l1;
            split2(acc[mf][nf][0], h0, l0);
            split2(acc[mf][nf][1], h1, l1);
            *(__nv_bfloat162*)&g_hbh[((size_t)(ba * N_ + i)) * E_ + e] = __nv_bfloat162(h0, h1);
            *(__nv_bfloat162*)&g_hbl[((size_t)(ba * N_ + i)) * E_ + e] = __nv_bfloat162(l0, l1);
            split2(acc[mf][nf][2], h0, l0);
            split2(acc[mf][nf][3], h1, l1);
            *(__nv_bfloat162*)&g_hbh[((size_t)(ba * N_ + i + 8)) * E_ + e] = __nv_bfloat162(h0, h1);
            *(__nv_bfloat162*)&g_hbl[((size_t)(ba * N_ + i + 8)) * E_ + e] = __nv_bfloat162(l0, l1);
            float2 ws = *(const float2*)(wsrc + head * E_ + e);
            float2 wd = *(const float2*)(wdst + head * E_ + e);
            float t0 = tanhf(acc[mf][nf][0]), t1 = tanhf(acc[mf][nf][1]);
            float t2 = tanhf(acc[mf][nf][2]), t3 = tanhf(acc[mf][nf][3]);
            sd[mf][0] += t0 * ws.x + t1 * ws.y;
            sd[mf][1] += t2 * ws.x + t3 * ws.y;
            dd[mf][0] += t0 * wd.x + t1 * wd.y;
            dd[mf][1] += t2 * wd.x + t3 * wd.y;
        }
#pragma unroll
        for (int rh = 0; rh < 2; ++rh) {
            float s = sd[mf][rh], d = dd[mf][rh];
            s += __shfl_xor_sync(0xffffffffu, s, 1);
            s += __shfl_xor_sync(0xffffffffu, s, 2);
            d += __shfl_xor_sync(0xffffffffu, d, 1);
            d += __shfl_xor_sync(0xffffffffu, d, 2);
            if (t == 0) {
                g_src[ba * N_ + i + rh * 8] = s;
                g_dst[ba * N_ + i + rh * 8] = d;
            }
        }
    }
}

// ---------------------------------------------------------------------------
// GEMM-2 (HMMA) + fused epilogue
// ---------------------------------------------------------------------------
__device__ __forceinline__ float blend_one(float accv, float hb, float att, float f) {
    float gt = 1.f / (1.f + __expf(-(accv + hb)));
    float fo = att > 0.f ? att : (__expf(att) - 1.f);
    return gt * fo + (1.f - gt) * f;
}

__global__ __launch_bounds__(256) void gemm2_tc_kernel(const float* __restrict__ feat,
                                                       const float* __restrict__ Hb,
                                                       float* __restrict__ out) {
    extern __shared__ char sm[];
    const int m0 = blockIdx.y << 7;
    const int n0 = blockIdx.x << 7;
    float acc[2][8][4];
#pragma unroll
    for (int mf = 0; mf < 2; ++mf)
#pragma unroll
        for (int nf = 0; nf < 8; ++nf)
#pragma unroll
            for (int q = 0; q < 4; ++q) acc[mf][nf][q] = 0.f;

    hmma_mainloop(acc, g_fh, g_fl, g_w2h, g_w2l, m0, n0, sm);

    const int warp = threadIdx.x >> 5, lane = threadIdx.x & 31;
    const int wm = warp & 3, wn = warp >> 2;
    const int g = lane >> 2, t = lane & 3;
#pragma unroll
    for (int mf = 0; mf < 2; ++mf)
#pragma unroll
        for (int nf = 0; nf < 8; ++nf) {
            const int m = m0 + wm * 32 + mf * 16 + g;
            const int n = n0 + wn * 64 + nf * 8 + 2 * t;
            float2 hb = *(const float2*)(Hb + n);
#pragma unroll
            for (int rr = 0; rr < 2; ++rr) {
                const int mm = m + rr * 8;
                float2 av = *(const float2*)(g_att + (size_t)mm * D_ + n);
                float2 fv = *(const float2*)(feat + (size_t)mm * D_ + n);
                float2 ov;
                ov.x = blend_one(acc[mf][nf][rr * 2 + 0], hb.x, av.x, fv.x);
                ov.y = blend_one(acc[mf][nf][rr * 2 + 1], hb.y, av.y, fv.y);
                *(float2*)(out + (size_t)mm * D_ + n) = ov;
            }
        }
}

// ---------------------------------------------------------------------------
// Attention (HMMA, factorized exp + unnormalized softmax + streamed H):
// P_ij = mask * ( src+dst>=0 ? Es_i*Ed_j : Es2_i*Ed2_j )  — no per-element MUFU.
// ---------------------------------------------------------------------------
#define HC_ROWB 144
#define HC_BUF_B (64 * HC_ROWB)          // 9216
#define P_ROWB 144
#define OFF_HCH 0                        // [2][64][144] hi        18432
#define OFF_HCL 18432                    // [2][64][144] lo        18432
#define OFF_PBH 36864                    // [128][144]             18432
#define OFF_PBL 55296                    //                        18432
#define OFF_SRC 73728                    // 128 f32 (512B)
#define OFF_DST 74240                    // 512 f32 (2048B)
#define OFF_MS  76288                    // 32x128 u16 (8192B)
#define OFF_SUM 84480                    // 128 f32 (512B)
#define OFF_ED  84992                    // 512 f32 (2048B)
#define OFF_ED2 87040                    // 512 f32 (2048B)
#define OFF_ES  89088                    // 128 f32 (512B)
#define OFF_ES2 89600                    // 128 f32 (512B)
#define ATT_SMEM_B 90112

__global__ __launch_bounds__(256, 2) void attn_kernel(const void* __restrict__ adjv,
                                                      const float* __restrict__ bbias) {
    extern __shared__ char sm[];
    const uint32_t smu = smem_u32(sm);
    char* Pbh = sm + OFF_PBH;
    char* Pbl = sm + OFF_PBL;
    float* s_src = (float*)(sm + OFF_SRC);
    float* s_dst = (float*)(sm + OFF_DST);
    float* s_sum = (float*)(sm + OFF_SUM);
    float* s_ed  = (float*)(sm + OFF_ED);
    float* s_ed2 = (float*)(sm + OFF_ED2);
    float* s_es  = (float*)(sm + OFF_ES);
    float* s_es2 = (float*)(sm + OFF_ES2);
    unsigned short* Ms = (unsigned short*)(sm + OFF_MS);   // [32 jwords][128 rows]

    const int tid = threadIdx.x;
    const int lane = tid & 31, warp = tid >> 5;
    const int b = blockIdx.z, a = blockIdx.y, it = blockIdx.x;
    const int ba = b * A_ + a;
    const int i0 = it * 128;

    const __nv_bfloat16* srcH = g_hbh + (size_t)ba * N_ * E_;
    const __nv_bfloat16* srcL = g_hbl + (size_t)ba * N_ * E_;

#define ISSUE_H(jc, buf) do {                                                \
    const int _j0 = (jc) * 64;                                               \
    _Pragma("unroll")                                                        \
    for (int _c = 0; _c < 2; ++_c) {                                         \
        const int _idx = tid * 2 + _c;                                       \
        const int _jr = _idx >> 3, _q = _idx & 7;                            \
        const uint32_t _dst = smu + OFF_HCH + (buf) * HC_BUF_B + _jr * HC_ROWB + _q * 16; \
        CP16(_dst, srcH + (size_t)(_j0 + _jr) * E_ + _q * 8);                \
        CP16(_dst + (OFF_HCL - OFF_HCH), srcL + (size_t)(_j0 + _jr) * E_ + _q * 8); \
    }                                                                        \
    CP_COMMIT(); } while (0)

    // ---- Phase A: issue chunk 0; load vectors ----
    ISSUE_H(0, 0);
    if (tid < 128) s_src[tid] = g_src[ba * N_ + i0 + tid];
    s_dst[tid] = g_dst[ba * N_ + tid];
    s_dst[tid + 256] = g_dst[ba * N_ + tid + 256];
    __syncthreads();   // s_src/s_dst visible

    // ---- Phase B: factorized-exp precompute + mask-bit packing ----
    {
        float d0 = s_dst[tid], d1 = s_dst[tid + 256];
        s_ed[tid] = __expf(d0);
        s_ed[tid + 256] = __expf(d1);
        s_ed2[tid] = __expf(0.2f * d0);
        s_ed2[tid + 256] = __expf(0.2f * d1);
        if (tid < 128) {
            float sv = s_src[tid];
            s_es[tid] = __expf(sv);
            s_es2[tid] = __expf(0.2f * sv);
        }
    }
    const int adj_int = g_adj_int;
    for (int rr = warp; rr < 128; rr += 8) {
        const size_t rowoff = (size_t)(b * N_ + i0 + rr) * N_;
        unsigned mbits = 0;
        if (adj_int) {
            const uint4* ap = (const uint4*)((const int*)adjv + rowoff + lane * 16);
#pragma unroll
            for (int q = 0; q < 4; ++q) {
                uint4 w = ap[q];
                mbits |= (w.x ? 1u : 0u) << (q * 4 + 0);
                mbits |= (w.y ? 1u : 0u) << (q * 4 + 1);
                mbits |= (w.z ? 1u : 0u) << (q * 4 + 2);
                mbits |= (w.w ? 1u : 0u) << (q * 4 + 3);
            }
        } else {
            uint4 w = *(const uint4*)((const uint8_t*)adjv + rowoff + lane * 16);
            unsigned ws[4] = {w.x, w.y, w.z, w.w};
#pragma unroll
            for (int q = 0; q < 4; ++q)
#pragma unroll
                for (int bq = 0; bq < 4; ++bq)
                    mbits |= (((ws[q] >> (8 * bq)) & 0xffu) ? 1u : 0u) << (q * 4 + bq);
        }
        Ms[lane * 128 + rr] = (unsigned short)mbits;
    }
    __syncthreads();   // Ms + exp tables visible

    // ---- Phase C ----
    const int wm = warp & 3, wn = warp >> 2;
    const int r = tid >> 1, jseg = (tid & 1) * 32;
    const float srcv = s_src[r];
    const float esv = s_es[r], es2v = s_es2[r];

    const int arow = (lane & 7) + ((lane >> 3) & 1) * 8;
    const int acolb = (lane >> 4) * 16;
    const uint32_t aP0 = smu + OFF_PBH + (uint32_t)(wm * 32 + arow) * P_ROWB + acolb;
    const int jrow = lane & 15;
    const int ecolb = (lane >> 4) * 16;
    const uint32_t bH0 = smu + OFF_HCH + (uint32_t)jrow * HC_ROWB + (wn * 32) * 2 + ecolb;

    float acc[2][4][4];
#pragma unroll
    for (int mf = 0; mf < 2; ++mf)
#pragma unroll
        for (int nf = 0; nf < 4; ++nf)
#pragma unroll
            for (int q = 0; q < 4; ++q) acc[mf][nf][q] = 0.f;

    float psum = 0.f;

    for (int jc = 0; jc < 8; ++jc) {
        // P chunk gen: factorized exp, no MUFU in the hot loop
        {
            const int jb = jc * 64 + jseg;
            uint32_t mw0 = Ms[(jb >> 4) * 128 + r];
            uint32_t mw1 = Ms[((jb >> 4) + 1) * 128 + r];
            uint32_t mbits = mw0 | (mw1 << 16);
#pragma unroll
            for (int q = 0; q < 32; q += 4) {
                float4 dv = *(const float4*)&s_dst[jb + q];
                float4 edv = *(const float4*)&s_ed[jb + q];
                float4 ed2v = *(const float4*)&s_ed2[jb + q];
                float p[4];
#pragma unroll
                for (int e = 0; e < 4; ++e) {
                    float v = srcv + (&dv.x)[e];
                    float pe = (v >= 0.f) ? esv * (&edv.x)[e] : es2v * (&ed2v.x)[e];
                    p[e] = ((mbits >> (q + e)) & 1u) ? pe : 0.f;
                    psum += p[e];
                }
                __nv_bfloat16 h0, l0, h1, l1;
                split2(p[0], h0, l0); split2(p[1], h1, l1);
                *(__nv_bfloat162*)(Pbh + r * P_ROWB + (jseg + q) * 2) = __nv_bfloat162(h0, h1);
                *(__nv_bfloat162*)(Pbl + r * P_ROWB + (jseg + q) * 2) = __nv_bfloat162(l0, l1);
                split2(p[2], h0, l0); split2(p[3], h1, l1);
                *(__nv_bfloat162*)(Pbh + r * P_ROWB + (jseg + q + 2) * 2) = __nv_bfloat162(h0, h1);
                *(__nv_bfloat162*)(Pbl + r * P_ROWB + (jseg + q + 2) * 2) = __nv_bfloat162(l0, l1);
            }
        }
        if (jc + 1 < 8) { ISSUE_H(jc + 1, (jc + 1) & 1); CP_WAIT1(); }
        else            { CP_WAIT0(); }
        __syncthreads();   // P visible + H chunk ready

        const uint32_t bbuf = bH0 + (jc & 1) * HC_BUF_B;
#pragma unroll
        for (int ks = 0; ks < 4; ++ks) {
            uint32_t ah[2][4], al[2][4], bh[2][4], bl[2][4];
#pragma unroll
            for (int mf = 0; mf < 2; ++mf) {
                ldsm_x4(ah[mf], aP0 + mf * 16 * P_ROWB + ks * 32);
                ldsm_x4(al[mf], aP0 + (OFF_PBL - OFF_PBH) + mf * 16 * P_ROWB + ks * 32);
            }
            const uint32_t bbase = bbuf + (uint32_t)(ks * 16) * HC_ROWB;
#pragma unroll
            for (int nfp = 0; nfp < 2; ++nfp) {
                ldsm_x4_t(bh[nfp], bbase + nfp * 32);
                ldsm_x4_t(bl[nfp], bbase + (OFF_HCL - OFF_HCH) + nfp * 32);
            }
#pragma unroll
            for (int nfp = 0; nfp < 2; ++nfp)
#pragma unroll
                for (int hf = 0; hf < 2; ++hf) {
                    const int nf = nfp * 2 + hf;
                    const uint32_t b0h = bh[nfp][hf * 2], b1h = bh[nfp][hf * 2 + 1];
                    const uint32_t b0l = bl[nfp][hf * 2], b1l = bl[nfp][hf * 2 + 1];
#pragma unroll
                    for (int mf = 0; mf < 2; ++mf) {
                        mma16816(acc[mf][nf], ah[mf][0], ah[mf][1], ah[mf][2], ah[mf][3], b0h, b1h);
                        mma16816(acc[mf][nf], al[mf][0], al[mf][1], al[mf][2], al[mf][3], b0h, b1h);
                        mma16816(acc[mf][nf], ah[mf][0], ah[mf][1], ah[mf][2], ah[mf][3], b0l, b1l);
                    }
                }
        }
        __syncthreads();   // done reading P/H before next-iter writes
    }
#undef ISSUE_H

    // row-sum: pair-reduce and publish
    psum += __shfl_xor_sync(0xffffffffu, psum, 1);
    if ((tid & 1) == 0) s_sum[r] = psum;
    __syncthreads();

    // ---- epilogue: normalize + bias + store ----
    const int g = lane >> 2, t = lane & 3;
#pragma unroll
    for (int mf = 0; mf < 2; ++mf) {
        const int rl = wm * 32 + mf * 16 + g;
        const float inv0 = __fdividef(1.f, s_sum[rl]);
        const float inv1 = __fdividef(1.f, s_sum[rl + 8]);
#pragma unroll
        for (int nf = 0; nf < 4; ++nf) {
            const int row = i0 + rl;
            const int col = wn * 32 + nf * 8 + 2 * t;
            float2 bias = *(const float2*)(bbias + col);
            float2 v0 = make_float2(fmaf(acc[mf][nf][0], inv0, bias.x),
                                    fmaf(acc[mf][nf][1], inv0, bias.y));
            float2 v1 = make_float2(fmaf(acc[mf][nf][2], inv1, bias.x),
                                    fmaf(acc[mf][nf][3], inv1, bias.y));
            *(float2*)&g_att[(size_t)(b * N_ + row) * D_ + a * E_ + col] = v0;
            *(float2*)&g_att[(size_t)(b * N_ + row + 8) * D_ + a * E_ + col] = v1;
        }
    }
}

// ---------------------------------------------------------------------------
extern "C" void kernel_launch(void* const* d_in, const int* in_sizes, int n_in,
                              void* d_out, int out_size) {
    const float* feat = (const float*)d_in[0];
    const void* adj = d_in[1];
    const float* W = (const float*)d_in[2];
    const float* bbias = (const float*)d_in[3];
    const float* wsrc = (const float*)d_in[4];
    const float* wdst = (const float*)d_in[5];
    const float* Hw = (const float*)d_in[6];
    const float* Hb = (const float*)d_in[7];
    float* out = (float*)d_out;

    detect_adj_kernel<<<1, 32>>>((const int*)adj);
    conv_feat_kernel<<<M_ * D_ / 1024, 256>>>(feat);
    conv_w1_kernel<<<dim3(A_, D_ / 64), 256>>>(W);
    conv_w2_kernel<<<D_ * D_ / 1024, 256>>>(Hw);

    cudaFuncSetAttribute(gemm1_tc_kernel, cudaFuncAttributeMaxDynamicSharedMemorySize, GEMM_SMEM);
    cudaFuncSetAttribute(gemm2_tc_kernel, cudaFuncAttributeMaxDynamicSharedMemorySize, GEMM_SMEM);
    cudaFuncSetAttribute(attn_kernel, cudaFuncAttributeMaxDynamicSharedMemorySize, ATT_SMEM_B);

    gemm1_tc_kernel<<<dim3(D_ / 128, M_ / 128), 256, GEMM_SMEM>>>(wsrc, wdst);

    attn_kernel<<<dim3(N_ / 128, A_, B_), 256, ATT_SMEM_B>>>(adj, bbias);

    gemm2_tc_kernel<<<dim3(D_ / 128, M_ / 128), 256, GEMM_SMEM>>>(feat, Hb, out);
}

// round 12
// speedup vs baseline: 1.0599x; 1.0599x over previous
#include <cuda_runtime.h>
#include <cuda_bf16.h>
#include <stdint.h>

// Problem constants
#define B_ 8
#define N_ 512
#define D_ 768
#define A_ 12
#define E_ 64
#define M_ (B_ * N_)   // 4096

// ---------------------------------------------------------------------------
// PTX helpers (all baseline features: valid for compute_103 virtual arch)
// ---------------------------------------------------------------------------
__device__ __forceinline__ uint32_t smem_u32(const void* p) {
    uint32_t a;
    asm("{ .reg .u64 t; cvta.to.shared.u64 t, %1; cvt.u32.u64 %0, t; }" : "=r"(a) : "l"(p));
    return a;
}
__device__ __forceinline__ void ldsm_x4(uint32_t* r, uint32_t addr) {
    asm volatile("ldmatrix.sync.aligned.m8n8.x4.shared.b16 {%0,%1,%2,%3}, [%4];"
        : "=r"(r[0]), "=r"(r[1]), "=r"(r[2]), "=r"(r[3]) : "r"(addr));
}
__device__ __forceinline__ void ldsm_x4_t(uint32_t* r, uint32_t addr) {
    asm volatile("ldmatrix.sync.aligned.m8n8.x4.trans.shared.b16 {%0,%1,%2,%3}, [%4];"
        : "=r"(r[0]), "=r"(r[1]), "=r"(r[2]), "=r"(r[3]) : "r"(addr));
}
#define CP16(dst, src) asm volatile("cp.async.cg.shared.global [%0], [%1], 16;" :: "r"(dst), "l"(src))
#define CP_COMMIT() asm volatile("cp.async.commit_group;" ::: "memory")
#define CP_WAIT1() asm volatile("cp.async.wait_group 1;" ::: "memory")
#define CP_WAIT0() asm volatile("cp.async.wait_group 0;" ::: "memory")

__device__ __forceinline__ void mma16816(float* c,
        uint32_t a0, uint32_t a1, uint32_t a2, uint32_t a3,
        uint32_t b0, uint32_t b1) {
    asm volatile(
        "mma.sync.aligned.m16n8k16.row.col.f32.bf16.bf16.f32 "
        "{%0,%1,%2,%3}, {%4,%5,%6,%7}, {%8,%9}, {%0,%1,%2,%3};"
        : "+f"(c[0]), "+f"(c[1]), "+f"(c[2]), "+f"(c[3])
        : "r"(a0), "r"(a1), "r"(a2), "r"(a3), "r"(b0), "r"(b1));
}

// ---------------------------------------------------------------------------
// Scratch (device globals: allocation-free)
// ---------------------------------------------------------------------------
__device__ float g_src[B_ * A_ * N_];
__device__ float g_dst[B_ * A_ * N_];
__device__ float g_att[B_ * N_ * D_];        // [b][i][a*64+e]
__device__ int   g_adj_int;
// h in bf16 hi/lo, layout [ba][j][e] (j = node, e = head dim)
__device__ __align__(16) __nv_bfloat16 g_hbh[B_ * A_ * N_ * E_];
__device__ __align__(16) __nv_bfloat16 g_hbl[B_ * A_ * N_ * E_];
// bf16 split GEMM operands (hi + lo)
__device__ __align__(16) __nv_bfloat16 g_fh[M_ * D_];
__device__ __align__(16) __nv_bfloat16 g_fl[M_ * D_];
__device__ __align__(16) __nv_bfloat16 g_w1h[D_ * D_];  // W^T: row n=a*64+e, col k=d
__device__ __align__(16) __nv_bfloat16 g_w1l[D_ * D_];
__device__ __align__(16) __nv_bfloat16 g_w2h[D_ * D_];  // Hw: row n, col k=d
__device__ __align__(16) __nv_bfloat16 g_w2l[D_ * D_];

// ---------------------------------------------------------------------------
// adj dtype detection
// ---------------------------------------------------------------------------
__global__ void detect_adj_kernel(const int* __restrict__ adj) {
    int ok = 1;
    for (int v = threadIdx.x; v < 1024; v += 32) {
        int w = adj[v];
        if (w != 0 && w != 1) ok = 0;
    }
#pragma unroll
    for (int o = 16; o; o >>= 1) ok &= __shfl_xor_sync(0xffffffffu, ok, o);
    if (threadIdx.x == 0) g_adj_int = ok;
}

// ---------------------------------------------------------------------------
// fp32 -> bf16 hi/lo split conversions
// ---------------------------------------------------------------------------
__device__ __forceinline__ void split2(float x, __nv_bfloat16& h, __nv_bfloat16& l) {
    h = __float2bfloat16(x);
    l = __float2bfloat16(x - __bfloat162float(h));
}

__global__ void conv_feat_kernel(const float* __restrict__ f) {
    const int g4 = (blockIdx.x * 256 + threadIdx.x) * 4;
    float4 v = *(const float4*)(f + g4);
    __nv_bfloat16 h0, h1, h2, h3, l0, l1, l2, l3;
    split2(v.x, h0, l0); split2(v.y, h1, l1); split2(v.z, h2, l2); split2(v.w, h3, l3);
    ((__nv_bfloat162*)(g_fh + g4))[0] = __nv_bfloat162(h0, h1);
    ((__nv_bfloat162*)(g_fh + g4))[1] = __nv_bfloat162(h2, h3);
    ((__nv_bfloat162*)(g_fl + g4))[0] = __nv_bfloat162(l0, l1);
    ((__nv_bfloat162*)(g_fl + g4))[1] = __nv_bfloat162(l2, l3);
}

// W [a][d][e] -> W^T rows n=a*64+e, cols d; smem-transpose for coalescing.
__global__ void conv_w1_kernel(const float* __restrict__ W) {
    __shared__ float tile[64][65];
    const int a = blockIdx.x, d0 = blockIdx.y * 64;
    const int tid = threadIdx.x;
#pragma unroll
    for (int it = 0; it < 16; ++it) {
        const int idx = it * 256 + tid;
        const int dd = idx >> 6, e = idx & 63;
        tile[dd][e] = W[(a * D_ + d0 + dd) * E_ + e];
    }
    __syncthreads();
#pragma unroll
    for (int it = 0; it < 16; ++it) {
        const int idx = it * 256 + tid;
        const int e = idx >> 6, dd = idx & 63;
        __nv_bfloat16 h, l;
        split2(tile[dd][e], h, l);
        g_w1h[(a * 64 + e) * D_ + d0 + dd] = h;
        g_w1l[(a * 64 + e) * D_ + d0 + dd] = l;
    }
}

__global__ void conv_w2_kernel(const float* __restrict__ Hw) {
    const int g4 = (blockIdx.x * 256 + threadIdx.x) * 4;
    float4 v = *(const float4*)(Hw + g4);
    __nv_bfloat16 h0, h1, h2, h3, l0, l1, l2, l3;
    split2(v.x, h0, l0); split2(v.y, h1, l1); split2(v.z, h2, l2); split2(v.w, h3, l3);
    ((__nv_bfloat162*)(g_w2h + g4))[0] = __nv_bfloat162(h0, h1);
    ((__nv_bfloat162*)(g_w2h + g4))[1] = __nv_bfloat162(h2, h3);
    ((__nv_bfloat162*)(g_w2l + g4))[0] = __nv_bfloat162(l0, l1);
    ((__nv_bfloat162*)(g_w2l + g4))[1] = __nv_bfloat162(l2, l3);
}

// ---------------------------------------------------------------------------
// HMMA bf16x3 GEMM: 128x128 block, 8 warps (4m x 2n), warp 32x64.
// ---------------------------------------------------------------------------
#define KC_ 32
#define NKC_ (D_ / KC_)          // 24
#define TROW_B 80
#define TILE_B (128 * TROW_B)    // 10240
#define BUF_B (4 * TILE_B)       // 40960
#define GEMM_SMEM (2 * BUF_B)    // 81920

__device__ __forceinline__ void hmma_mainloop(
        float acc[2][8][4],
        const __nv_bfloat16* __restrict__ Ah, const __nv_bfloat16* __restrict__ Al,
        const __nv_bfloat16* __restrict__ Bh, const __nv_bfloat16* __restrict__ Bl,
        int m0, int n0, char* sm) {
    const int tid = threadIdx.x;
    const int warp = tid >> 5, lane = tid & 31;
    const int wm = warp & 3, wn = warp >> 2;

    const int lr = tid >> 1;
    const int lce = (tid & 1) * 16;
    const uint32_t sto = (uint32_t)lr * TROW_B + (tid & 1) * 32;
    const uint32_t smu = smem_u32(sm);

    const __nv_bfloat16* pAh = Ah + (size_t)(m0 + lr) * D_ + lce;
    const __nv_bfloat16* pAl = Al + (size_t)(m0 + lr) * D_ + lce;
    const __nv_bfloat16* pBh = Bh + (size_t)(n0 + lr) * D_ + lce;
    const __nv_bfloat16* pBl = Bl + (size_t)(n0 + lr) * D_ + lce;

#define ISSUE(kc, buf) do {                                                  \
    uint32_t _bb = smu + (buf) * BUF_B + sto;                                \
    const int _o = (kc) * KC_;                                               \
    CP16(_bb, pAh + _o);                 CP16(_bb + 16, pAh + _o + 8);       \
    CP16(_bb + TILE_B, pAl + _o);        CP16(_bb + TILE_B + 16, pAl + _o + 8); \
    CP16(_bb + 2 * TILE_B, pBh + _o);    CP16(_bb + 2 * TILE_B + 16, pBh + _o + 8); \
    CP16(_bb + 3 * TILE_B, pBl + _o);    CP16(_bb + 3 * TILE_B + 16, pBl + _o + 8); \
    CP_COMMIT(); } while (0)

    ISSUE(0, 0);

    const int arow = (lane & 7) + ((lane >> 3) & 1) * 8;
    const int acolb = (lane >> 4) * 16;
    const int brow = (lane & 7) + (lane >> 4) * 8;
    const int bcolb = ((lane >> 3) & 1) * 16;

    for (int kc = 0; kc < NKC_; ++kc) {
        if (kc + 1 < NKC_) { ISSUE(kc + 1, (kc + 1) & 1); CP_WAIT1(); }
        else               { CP_WAIT0(); }
        __syncthreads();
        const uint32_t bufb = smu + (kc & 1) * BUF_B;
        const uint32_t aA0 = bufb + (uint32_t)(wm * 32 + arow) * TROW_B + acolb;
        const uint32_t bB0 = bufb + 2 * TILE_B + (uint32_t)(wn * 64 + brow) * TROW_B + bcolb;
#pragma unroll
        for (int ks = 0; ks < 2; ++ks) {
            uint32_t ah[2][4], al[2][4], bh[4][4], bl[4][4];
#pragma unroll
            for (int mf = 0; mf < 2; ++mf) {
                ldsm_x4(ah[mf], aA0 + mf * 16 * TROW_B + ks * 32);
                ldsm_x4(al[mf], aA0 + TILE_B + mf * 16 * TROW_B + ks * 32);
            }
#pragma unroll
            for (int nfp = 0; nfp < 4; ++nfp) {
                ldsm_x4(bh[nfp], bB0 + nfp * 16 * TROW_B + ks * 32);
                ldsm_x4(bl[nfp], bB0 + TILE_B + nfp * 16 * TROW_B + ks * 32);
            }
#pragma unroll
            for (int nfp = 0; nfp < 4; ++nfp)
#pragma unroll
                for (int hf = 0; hf < 2; ++hf) {
                    const int nf = nfp * 2 + hf;
                    const uint32_t b0h = bh[nfp][hf * 2], b1h = bh[nfp][hf * 2 + 1];
                    const uint32_t b0l = bl[nfp][hf * 2], b1l = bl[nfp][hf * 2 + 1];
#pragma unroll
                    for (int mf = 0; mf < 2; ++mf) {
                        mma16816(acc[mf][nf], ah[mf][0], ah[mf][1], ah[mf][2], ah[mf][3], b0h, b1h);
                        mma16816(acc[mf][nf], al[mf][0], al[mf][1], al[mf][2], al[mf][3], b0h, b1h);
                        mma16816(acc[mf][nf], ah[mf][0], ah[mf][1], ah[mf][2], ah[mf][3], b0l, b1l);
                    }
                }
        }
        __syncthreads();
    }
#undef ISSUE
}

// ---------------------------------------------------------------------------
// GEMM-1 (HMMA): h = feat @ W^T; epilogue splits h + fused src/dst logits.
// ---------------------------------------------------------------------------
__global__ __launch_bounds__(256) void gemm1_tc_kernel(const float* __restrict__ wsrc,
                                                       const float* __restrict__ wdst) {
    extern __shared__ char sm[];
    const int m0 = blockIdx.y << 7;
    const int n0 = blockIdx.x << 7;
    float acc[2][8][4];
#pragma unroll
    for (int mf = 0; mf < 2; ++mf)
#pragma unroll
        for (int nf = 0; nf < 8; ++nf)
#pragma unroll
            for (int q = 0; q < 4; ++q) acc[mf][nf][q] = 0.f;

    hmma_mainloop(acc, g_fh, g_fl, g_w1h, g_w1l, m0, n0, sm);

    const int warp = threadIdx.x >> 5, lane = threadIdx.x & 31;
    const int wm = warp & 3, wn = warp >> 2;
    const int g = lane >> 2, t = lane & 3;
    const int head = (n0 >> 6) + wn;

    float sd[2][2], dd[2][2];
#pragma unroll
    for (int mf = 0; mf < 2; ++mf) sd[mf][0] = sd[mf][1] = dd[mf][0] = dd[mf][1] = 0.f;

#pragma unroll
    for (int mf = 0; mf < 2; ++mf) {
        const int m = m0 + wm * 32 + mf * 16 + g;
        const int b = m >> 9, i = m & (N_ - 1);
        const int ba = b * A_ + head;
#pragma unroll
        for (int nf = 0; nf < 8; ++nf) {
            const int e = nf * 8 + 2 * t;
            __nv_bfloat16 h0, l0, h1, l1;
            split2(acc[mf][nf][0], h0, l0);
            split2(acc[mf][nf][1], h1, l1);
            *(__nv_bfloat162*)&g_hbh[((size_t)(ba * N_ + i)) * E_ + e] = __nv_bfloat162(h0, h1);
            *(__nv_bfloat162*)&g_hbl[((size_t)(ba * N_ + i)) * E_ + e] = __nv_bfloat162(l0, l1);
            split2(acc[mf][nf][2], h0, l0);
            split2(acc[mf][nf][3], h1, l1);
            *(__nv_bfloat162*)&g_hbh[((size_t)(ba * N_ + i + 8)) * E_ + e] = __nv_bfloat162(h0, h1);
            *(__nv_bfloat162*)&g_hbl[((size_t)(ba * N_ + i + 8)) * E_ + e] = __nv_bfloat162(l0, l1);
            float2 ws = *(const float2*)(wsrc + head * E_ + e);
            float2 wd = *(const float2*)(wdst + head * E_ + e);
            float t0 = tanhf(acc[mf][nf][0]), t1 = tanhf(acc[mf][nf][1]);
            float t2 = tanhf(acc[mf][nf][2]), t3 = tanhf(acc[mf][nf][3]);
            sd[mf][0] += t0 * ws.x + t1 * ws.y;
            sd[mf][1] += t2 * ws.x + t3 * ws.y;
            dd[mf][0] += t0 * wd.x + t1 * wd.y;
            dd[mf][1] += t2 * wd.x + t3 * wd.y;
        }
#pragma unroll
        for (int rh = 0; rh < 2; ++rh) {
            float s = sd[mf][rh], d = dd[mf][rh];
            s += __shfl_xor_sync(0xffffffffu, s, 1);
            s += __shfl_xor_sync(0xffffffffu, s, 2);
            d += __shfl_xor_sync(0xffffffffu, d, 1);
            d += __shfl_xor_sync(0xffffffffu, d, 2);
            if (t == 0) {
                g_src[ba * N_ + i + rh * 8] = s;
                g_dst[ba * N_ + i + rh * 8] = d;
            }
        }
    }
}

// ---------------------------------------------------------------------------
// GEMM-2 (HMMA) + fused epilogue
// ---------------------------------------------------------------------------
__device__ __forceinline__ float blend_one(float accv, float hb, float att, float f) {
    float gt = 1.f / (1.f + __expf(-(accv + hb)));
    float fo = att > 0.f ? att : (__expf(att) - 1.f);
    return gt * fo + (1.f - gt) * f;
}

__global__ __launch_bounds__(256) void gemm2_tc_kernel(const float* __restrict__ feat,
                                                       const float* __restrict__ Hb,
                                                       float* __restrict__ out) {
    extern __shared__ char sm[];
    const int m0 = blockIdx.y << 7;
    const int n0 = blockIdx.x << 7;
    float acc[2][8][4];
#pragma unroll
    for (int mf = 0; mf < 2; ++mf)
#pragma unroll
        for (int nf = 0; nf < 8; ++nf)
#pragma unroll
            for (int q = 0; q < 4; ++q) acc[mf][nf][q] = 0.f;

    hmma_mainloop(acc, g_fh, g_fl, g_w2h, g_w2l, m0, n0, sm);

    const int warp = threadIdx.x >> 5, lane = threadIdx.x & 31;
    const int wm = warp & 3, wn = warp >> 2;
    const int g = lane >> 2, t = lane & 3;
#pragma unroll
    for (int mf = 0; mf < 2; ++mf)
#pragma unroll
        for (int nf = 0; nf < 8; ++nf) {
            const int m = m0 + wm * 32 + mf * 16 + g;
            const int n = n0 + wn * 64 + nf * 8 + 2 * t;
            float2 hb = *(const float2*)(Hb + n);
#pragma unroll
            for (int rr = 0; rr < 2; ++rr) {
                const int mm = m + rr * 8;
                float2 av = *(const float2*)(g_att + (size_t)mm * D_ + n);
                float2 fv = *(const float2*)(feat + (size_t)mm * D_ + n);
                float2 ov;
                ov.x = blend_one(acc[mf][nf][rr * 2 + 0], hb.x, av.x, fv.x);
                ov.y = blend_one(acc[mf][nf][rr * 2 + 1], hb.y, av.y, fv.y);
                *(float2*)(out + (size_t)mm * D_ + n) = ov;
            }
        }
}

// ---------------------------------------------------------------------------
// Attention (HMMA, i-tile 64 for 3 CTAs/SM + 86% wave utilization):
// Block = (itile of 64, a, b), 8 warps (2m x 4n), warp out tile 32x16.
// Phase A: vectors; issue H chunk 0 (cp.async double buffer, 64 j-rows).
// Phase B: mask-bit packing.
// Phase C: per 64-j chunk: P = exp(leaky(src+dst)) masked (unnormalized,
//          direct __expf), row-sum in registers; HMMA Ph@Hh + Pl@Hh + Ph@Hl.
// Epilogue: out = acc / rowsum + bias.
// ---------------------------------------------------------------------------
#define IT_ 64
#define HC_ROWB 144
#define HC_BUF_B (64 * HC_ROWB)          // 9216
#define P_ROWB 144
#define OFF_HCH 0                        // [2][64][144]           18432
#define OFF_HCL 18432                    //                        18432
#define OFF_PBH 36864                    // [64][144]              9216
#define OFF_PBL 46080                    //                        9216
#define OFF_SRC 55296                    // 64 f32 (256B)
#define OFF_DST 55552                    // 512 f32 (2048B)
#define OFF_MS  57600                    // 32x64 u16 (4096B)
#define OFF_SUM 61696                    // 64 f32 (256B)
#define ATT_SMEM_B 61952

__global__ __launch_bounds__(256, 3) void attn_kernel(const void* __restrict__ adjv,
                                                      const float* __restrict__ bbias) {
    extern __shared__ char sm[];
    const uint32_t smu = smem_u32(sm);
    char* Pbh = sm + OFF_PBH;
    char* Pbl = sm + OFF_PBL;
    float* s_src = (float*)(sm + OFF_SRC);
    float* s_dst = (float*)(sm + OFF_DST);
    float* s_sum = (float*)(sm + OFF_SUM);
    unsigned short* Ms = (unsigned short*)(sm + OFF_MS);   // [32 jwords][64 rows]

    const int tid = threadIdx.x;
    const int lane = tid & 31, warp = tid >> 5;
    const int b = blockIdx.z, a = blockIdx.y, it = blockIdx.x;
    const int ba = b * A_ + a;
    const int i0 = it * IT_;

    const __nv_bfloat16* srcH = g_hbh + (size_t)ba * N_ * E_;
    const __nv_bfloat16* srcL = g_hbl + (size_t)ba * N_ * E_;

#define ISSUE_H(jc, buf) do {                                                \
    const int _j0 = (jc) * 64;                                               \
    _Pragma("unroll")                                                        \
    for (int _c = 0; _c < 2; ++_c) {                                         \
        const int _idx = tid * 2 + _c;                                       \
        const int _jr = _idx >> 3, _q = _idx & 7;                            \
        const uint32_t _dst = smu + OFF_HCH + (buf) * HC_BUF_B + _jr * HC_ROWB + _q * 16; \
        CP16(_dst, srcH + (size_t)(_j0 + _jr) * E_ + _q * 8);                \
        CP16(_dst + (OFF_HCL - OFF_HCH), srcL + (size_t)(_j0 + _jr) * E_ + _q * 8); \
    }                                                                        \
    CP_COMMIT(); } while (0)

    // ---- Phase A: issue chunk 0; load vectors ----
    ISSUE_H(0, 0);
    if (tid < IT_) s_src[tid] = g_src[ba * N_ + i0 + tid];
    s_dst[tid] = g_dst[ba * N_ + tid];
    s_dst[tid + 256] = g_dst[ba * N_ + tid + 256];
    __syncthreads();   // s_src/s_dst visible

    // ---- Phase B: mask-bit packing ----
    const int adj_int = g_adj_int;
    for (int rr = warp; rr < IT_; rr += 8) {
        const size_t rowoff = (size_t)(b * N_ + i0 + rr) * N_;
        unsigned mbits = 0;
        if (adj_int) {
            const uint4* ap = (const uint4*)((const int*)adjv + rowoff + lane * 16);
#pragma unroll
            for (int q = 0; q < 4; ++q) {
                uint4 w = ap[q];
                mbits |= (w.x ? 1u : 0u) << (q * 4 + 0);
                mbits |= (w.y ? 1u : 0u) << (q * 4 + 1);
                mbits |= (w.z ? 1u : 0u) << (q * 4 + 2);
                mbits |= (w.w ? 1u : 0u) << (q * 4 + 3);
            }
        } else {
            uint4 w = *(const uint4*)((const uint8_t*)adjv + rowoff + lane * 16);
            unsigned ws[4] = {w.x, w.y, w.z, w.w};
#pragma unroll
            for (int q = 0; q < 4; ++q)
#pragma unroll
                for (int bq = 0; bq < 4; ++bq)
                    mbits |= (((ws[q] >> (8 * bq)) & 0xffu) ? 1u : 0u) << (q * 4 + bq);
        }
        Ms[lane * IT_ + rr] = (unsigned short)mbits;
    }
    __syncthreads();   // Ms visible

    // ---- Phase C ----
    const int wm = warp & 1, wn = warp >> 1;        // 2m x 4n warps
    const int r = tid >> 2, jseg = (tid & 3) * 16;  // P-gen: row r, 16 j per chunk
    const float srcv = s_src[r];

    const int arow = (lane & 7) + ((lane >> 3) & 1) * 8;
    const int acolb = (lane >> 4) * 16;
    const uint32_t aP0 = smu + OFF_PBH + (uint32_t)(wm * 32 + arow) * P_ROWB + acolb;
    const int jrow = lane & 15;
    const int ecolb = (lane >> 4) * 16;
    const uint32_t bH0 = smu + OFF_HCH + (uint32_t)jrow * HC_ROWB + (wn * 16) * 2 + ecolb;

    float acc[2][2][4];
#pragma unroll
    for (int mf = 0; mf < 2; ++mf)
#pragma unroll
        for (int nf = 0; nf < 2; ++nf)
#pragma unroll
            for (int q = 0; q < 4; ++q) acc[mf][nf][q] = 0.f;

    float psum = 0.f;

    for (int jc = 0; jc < 8; ++jc) {
        // P chunk gen (unnormalized exp; accumulate partial row sum)
        {
            const int jb = jc * 64 + jseg;
            uint32_t mbits = Ms[(jb >> 4) * IT_ + r];
#pragma unroll
            for (int q = 0; q < 16; q += 4) {
                float4 dv = *(const float4*)&s_dst[jb + q];
                float p[4];
#pragma unroll
                for (int e = 0; e < 4; ++e) {
                    float v = srcv + (&dv.x)[e];
                    v = v >= 0.f ? v : 0.2f * v;
                    p[e] = ((mbits >> (q + e)) & 1u) ? __expf(v) : 0.f;
                    psum += p[e];
                }
                __nv_bfloat16 h0, l0, h1, l1;
                split2(p[0], h0, l0); split2(p[1], h1, l1);
                *(__nv_bfloat162*)(Pbh + r * P_ROWB + (jseg + q) * 2) = __nv_bfloat162(h0, h1);
                *(__nv_bfloat162*)(Pbl + r * P_ROWB + (jseg + q) * 2) = __nv_bfloat162(l0, l1);
                split2(p[2], h0, l0); split2(p[3], h1, l1);
                *(__nv_bfloat162*)(Pbh + r * P_ROWB + (jseg + q + 2) * 2) = __nv_bfloat162(h0, h1);
                *(__nv_bfloat162*)(Pbl + r * P_ROWB + (jseg + q + 2) * 2) = __nv_bfloat162(l0, l1);
            }
        }
        if (jc + 1 < 8) { ISSUE_H(jc + 1, (jc + 1) & 1); CP_WAIT1(); }
        else            { CP_WAIT0(); }
        __syncthreads();   // P visible + H chunk ready

        const uint32_t bbuf = bH0 + (jc & 1) * HC_BUF_B;
#pragma unroll
        for (int ks = 0; ks < 4; ++ks) {
            uint32_t ah[2][4], al[2][4], bh[4], bl[4];
#pragma unroll
            for (int mf = 0; mf < 2; ++mf) {
                ldsm_x4(ah[mf], aP0 + mf * 16 * P_ROWB + ks * 32);
                ldsm_x4(al[mf], aP0 + (OFF_PBL - OFF_PBH) + mf * 16 * P_ROWB + ks * 32);
            }
            const uint32_t bbase = bbuf + (uint32_t)(ks * 16) * HC_ROWB;
            ldsm_x4_t(bh, bbase);
            ldsm_x4_t(bl, bbase + (OFF_HCL - OFF_HCH));
#pragma unroll
            for (int nf = 0; nf < 2; ++nf) {
                const uint32_t b0h = bh[nf * 2], b1h = bh[nf * 2 + 1];
                const uint32_t b0l = bl[nf * 2], b1l = bl[nf * 2 + 1];
#pragma unroll
                for (int mf = 0; mf < 2; ++mf) {
                    mma16816(acc[mf][nf], ah[mf][0], ah[mf][1], ah[mf][2], ah[mf][3], b0h, b1h);
                    mma16816(acc[mf][nf], al[mf][0], al[mf][1], al[mf][2], al[mf][3], b0h, b1h);
                    mma16816(acc[mf][nf], ah[mf][0], ah[mf][1], ah[mf][2], ah[mf][3], b0l, b1l);
                }
            }
        }
        __syncthreads();   // done reading P/H before next-iter writes
    }
#undef ISSUE_H

    // row-sum: quad-reduce and publish
    psum += __shfl_xor_sync(0xffffffffu, psum, 1);
    psum += __shfl_xor_sync(0xffffffffu, psum, 2);
    if ((tid & 3) == 0) s_sum[r] = psum;
    __syncthreads();

    // ---- epilogue: normalize + bias + store ----
    const int g = lane >> 2, t = lane & 3;
#pragma unroll
    for (int mf = 0; mf < 2; ++mf) {
        const int rl = wm * 32 + mf * 16 + g;
        const float inv0 = __fdividef(1.f, s_sum[rl]);
        const float inv1 = __fdividef(1.f, s_sum[rl + 8]);
#pragma unroll
        for (int nf = 0; nf < 2; ++nf) {
            const int row = i0 + rl;
            const int col = wn * 16 + nf * 8 + 2 * t;
            float2 bias = *(const float2*)(bbias + col);
            float2 v0 = make_float2(fmaf(acc[mf][nf][0], inv0, bias.x),
                                    fmaf(acc[mf][nf][1], inv0, bias.y));
            float2 v1 = make_float2(fmaf(acc[mf][nf][2], inv1, bias.x),
                                    fmaf(acc[mf][nf][3], inv1, bias.y));
            *(float2*)&g_att[(size_t)(b * N_ + row) * D_ + a * E_ + col] = v0;
            *(float2*)&g_att[(size_t)(b * N_ + row + 8) * D_ + a * E_ + col] = v1;
        }
    }
}

// ---------------------------------------------------------------------------
extern "C" void kernel_launch(void* const* d_in, const int* in_sizes, int n_in,
                              void* d_out, int out_size) {
    const float* feat = (const float*)d_in[0];
    const void* adj = d_in[1];
    const float* W = (const float*)d_in[2];
    const float* bbias = (const float*)d_in[3];
    const float* wsrc = (const float*)d_in[4];
    const float* wdst = (const float*)d_in[5];
    const float* Hw = (const float*)d_in[6];
    const float* Hb = (const float*)d_in[7];
    float* out = (float*)d_out;

    detect_adj_kernel<<<1, 32>>>((const int*)adj);
    conv_feat_kernel<<<M_ * D_ / 1024, 256>>>(feat);
    conv_w1_kernel<<<dim3(A_, D_ / 64), 256>>>(W);
    conv_w2_kernel<<<D_ * D_ / 1024, 256>>>(Hw);

    cudaFuncSetAttribute(gemm1_tc_kernel, cudaFuncAttributeMaxDynamicSharedMemorySize, GEMM_SMEM);
    cudaFuncSetAttribute(gemm2_tc_kernel, cudaFuncAttributeMaxDynamicSharedMemorySize, GEMM_SMEM);
    cudaFuncSetAttribute(attn_kernel, cudaFuncAttributeMaxDynamicSharedMemorySize, ATT_SMEM_B);

    gemm1_tc_kernel<<<dim3(D_ / 128, M_ / 128), 256, GEMM_SMEM>>>(wsrc, wdst);

    attn_kernel<<<dim3(N_ / IT_, A_, B_), 256, ATT_SMEM_B>>>(adj, bbias);

    gemm2_tc_kernel<<<dim3(D_ / 128, M_ / 128), 256, GEMM_SMEM>>>(feat, Hb, out);
}

// round 13
// speedup vs baseline: 1.3625x; 1.2855x over previous
#include <cuda_runtime.h>
#include <cuda_bf16.h>
#include <stdint.h>

// Problem constants
#define B_ 8
#define N_ 512
#define D_ 768
#define A_ 12
#define E_ 64
#define M_ (B_ * N_)   // 4096

// ---------------------------------------------------------------------------
// PTX helpers (all baseline features: valid for compute_103 virtual arch)
// ---------------------------------------------------------------------------
__device__ __forceinline__ uint32_t smem_u32(const void* p) {
    uint32_t a;
    asm("{ .reg .u64 t; cvta.to.shared.u64 t, %1; cvt.u32.u64 %0, t; }" : "=r"(a) : "l"(p));
    return a;
}
__device__ __forceinline__ void ldsm_x4(uint32_t* r, uint32_t addr) {
    asm volatile("ldmatrix.sync.aligned.m8n8.x4.shared.b16 {%0,%1,%2,%3}, [%4];"
        : "=r"(r[0]), "=r"(r[1]), "=r"(r[2]), "=r"(r[3]) : "r"(addr));
}
__device__ __forceinline__ void ldsm_x4_t(uint32_t* r, uint32_t addr) {
    asm volatile("ldmatrix.sync.aligned.m8n8.x4.trans.shared.b16 {%0,%1,%2,%3}, [%4];"
        : "=r"(r[0]), "=r"(r[1]), "=r"(r[2]), "=r"(r[3]) : "r"(addr));
}
#define CP16(dst, src) asm volatile("cp.async.cg.shared.global [%0], [%1], 16;" :: "r"(dst), "l"(src))
#define CP_COMMIT() asm volatile("cp.async.commit_group;" ::: "memory")
#define CP_WAIT1() asm volatile("cp.async.wait_group 1;" ::: "memory")
#define CP_WAIT0() asm volatile("cp.async.wait_group 0;" ::: "memory")

__device__ __forceinline__ void mma16816(float* c,
        uint32_t a0, uint32_t a1, uint32_t a2, uint32_t a3,
        uint32_t b0, uint32_t b1) {
    asm volatile(
        "mma.sync.aligned.m16n8k16.row.col.f32.bf16.bf16.f32 "
        "{%0,%1,%2,%3}, {%4,%5,%6,%7}, {%8,%9}, {%0,%1,%2,%3};"
        : "+f"(c[0]), "+f"(c[1]), "+f"(c[2]), "+f"(c[3])
        : "r"(a0), "r"(a1), "r"(a2), "r"(a3), "r"(b0), "r"(b1));
}

// ---------------------------------------------------------------------------
// Scratch (device globals: allocation-free)
// ---------------------------------------------------------------------------
__device__ float g_src[B_ * A_ * N_];
__device__ float g_dst[B_ * A_ * N_];
__device__ float g_gate[B_ * N_ * D_];       // sigmoid(feat @ Hw^T + Hb)
__device__ int   g_adj_int;
// h in bf16 hi/lo, layout [ba][j][e]
__device__ __align__(16) __nv_bfloat16 g_hbh[B_ * A_ * N_ * E_];
__device__ __align__(16) __nv_bfloat16 g_hbl[B_ * A_ * N_ * E_];
// bf16 split GEMM operands (hi + lo)
__device__ __align__(16) __nv_bfloat16 g_fh[M_ * D_];
__device__ __align__(16) __nv_bfloat16 g_fl[M_ * D_];
__device__ __align__(16) __nv_bfloat16 g_w1h[D_ * D_];  // W^T: row n=a*64+e, col k=d
__device__ __align__(16) __nv_bfloat16 g_w1l[D_ * D_];
__device__ __align__(16) __nv_bfloat16 g_w2h[D_ * D_];  // Hw: row n, col k=d
__device__ __align__(16) __nv_bfloat16 g_w2l[D_ * D_];

// ---------------------------------------------------------------------------
// fp32 -> bf16 hi/lo split
// ---------------------------------------------------------------------------
__device__ __forceinline__ void split2(float x, __nv_bfloat16& h, __nv_bfloat16& l) {
    h = __float2bfloat16(x);
    l = __float2bfloat16(x - __bfloat162float(h));
}

// ---------------------------------------------------------------------------
// Combined prep kernel: feat conv | w2 conv | w1 conv | adj detect
// grid = 3072 + 576 + 144 + 1 = 3793 blocks of 256
// ---------------------------------------------------------------------------
#define PREP_FEAT 3072
#define PREP_W2 (PREP_FEAT + 576)
#define PREP_W1 (PREP_W2 + 144)
#define PREP_GRID (PREP_W1 + 1)

__global__ void prep_kernel(const float* __restrict__ f, const float* __restrict__ W,
                            const float* __restrict__ Hw, const int* __restrict__ adj) {
    __shared__ float tile[64][65];
    const int bx = blockIdx.x;
    const int tid = threadIdx.x;
    if (bx < PREP_FEAT) {
        const int g4 = (bx * 256 + tid) * 4;
        float4 v = *(const float4*)(f + g4);
        __nv_bfloat16 h0, h1, h2, h3, l0, l1, l2, l3;
        split2(v.x, h0, l0); split2(v.y, h1, l1); split2(v.z, h2, l2); split2(v.w, h3, l3);
        ((__nv_bfloat162*)(g_fh + g4))[0] = __nv_bfloat162(h0, h1);
        ((__nv_bfloat162*)(g_fh + g4))[1] = __nv_bfloat162(h2, h3);
        ((__nv_bfloat162*)(g_fl + g4))[0] = __nv_bfloat162(l0, l1);
        ((__nv_bfloat162*)(g_fl + g4))[1] = __nv_bfloat162(l2, l3);
    } else if (bx < PREP_W2) {
        const int g4 = ((bx - PREP_FEAT) * 256 + tid) * 4;
        float4 v = *(const float4*)(Hw + g4);
        __nv_bfloat16 h0, h1, h2, h3, l0, l1, l2, l3;
        split2(v.x, h0, l0); split2(v.y, h1, l1); split2(v.z, h2, l2); split2(v.w, h3, l3);
        ((__nv_bfloat162*)(g_w2h + g4))[0] = __nv_bfloat162(h0, h1);
        ((__nv_bfloat162*)(g_w2h + g4))[1] = __nv_bfloat162(h2, h3);
        ((__nv_bfloat162*)(g_w2l + g4))[0] = __nv_bfloat162(l0, l1);
        ((__nv_bfloat162*)(g_w2l + g4))[1] = __nv_bfloat162(l2, l3);
    } else if (bx < PREP_W1) {
        const int idx0 = bx - PREP_W2;
        const int a = idx0 / (D_ / 64), d0 = (idx0 % (D_ / 64)) * 64;
#pragma unroll
        for (int it = 0; it < 16; ++it) {
            const int idx = it * 256 + tid;
            const int dd = idx >> 6, e = idx & 63;
            tile[dd][e] = W[(a * D_ + d0 + dd) * E_ + e];
        }
        __syncthreads();
#pragma unroll
        for (int it = 0; it < 16; ++it) {
            const int idx = it * 256 + tid;
            const int e = idx >> 6, dd = idx & 63;
            __nv_bfloat16 h, l;
            split2(tile[dd][e], h, l);
            g_w1h[(a * 64 + e) * D_ + d0 + dd] = h;
            g_w1l[(a * 64 + e) * D_ + d0 + dd] = l;
        }
    } else {
        if (tid < 32) {
            int ok = 1;
            for (int v = tid; v < 1024; v += 32) {
                int w = adj[v];
                if (w != 0 && w != 1) ok = 0;
            }
#pragma unroll
            for (int o = 16; o; o >>= 1) ok &= __shfl_xor_sync(0xffffffffu, ok, o);
            if (tid == 0) g_adj_int = ok;
        }
    }
}

// ---------------------------------------------------------------------------
// HMMA bf16x3 GEMM mainloop: 128x128 block, 8 warps (4m x 2n), warp 32x64.
// ---------------------------------------------------------------------------
#define KC_ 32
#define NKC_ (D_ / KC_)          // 24
#define TROW_B 80
#define TILE_B (128 * TROW_B)    // 10240
#define BUF_B (4 * TILE_B)       // 40960
#define GEMM_SMEM (2 * BUF_B)    // 81920

__device__ __forceinline__ void hmma_mainloop(
        float acc[2][8][4],
        const __nv_bfloat16* __restrict__ Ah, const __nv_bfloat16* __restrict__ Al,
        const __nv_bfloat16* __restrict__ Bh, const __nv_bfloat16* __restrict__ Bl,
        int m0, int n0, char* sm) {
    const int tid = threadIdx.x;
    const int warp = tid >> 5, lane = tid & 31;
    const int wm = warp & 3, wn = warp >> 2;

    const int lr = tid >> 1;
    const int lce = (tid & 1) * 16;
    const uint32_t sto = (uint32_t)lr * TROW_B + (tid & 1) * 32;
    const uint32_t smu = smem_u32(sm);

    const __nv_bfloat16* pAh = Ah + (size_t)(m0 + lr) * D_ + lce;
    const __nv_bfloat16* pAl = Al + (size_t)(m0 + lr) * D_ + lce;
    const __nv_bfloat16* pBh = Bh + (size_t)(n0 + lr) * D_ + lce;
    const __nv_bfloat16* pBl = Bl + (size_t)(n0 + lr) * D_ + lce;

#define ISSUE(kc, buf) do {                                                  \
    uint32_t _bb = smu + (buf) * BUF_B + sto;                                \
    const int _o = (kc) * KC_;                                               \
    CP16(_bb, pAh + _o);                 CP16(_bb + 16, pAh + _o + 8);       \
    CP16(_bb + TILE_B, pAl + _o);        CP16(_bb + TILE_B + 16, pAl + _o + 8); \
    CP16(_bb + 2 * TILE_B, pBh + _o);    CP16(_bb + 2 * TILE_B + 16, pBh + _o + 8); \
    CP16(_bb + 3 * TILE_B, pBl + _o);    CP16(_bb + 3 * TILE_B + 16, pBl + _o + 8); \
    CP_COMMIT(); } while (0)

    ISSUE(0, 0);

    const int arow = (lane & 7) + ((lane >> 3) & 1) * 8;
    const int acolb = (lane >> 4) * 16;
    const int brow = (lane & 7) + (lane >> 4) * 8;
    const int bcolb = ((lane >> 3) & 1) * 16;

    for (int kc = 0; kc < NKC_; ++kc) {
        if (kc + 1 < NKC_) { ISSUE(kc + 1, (kc + 1) & 1); CP_WAIT1(); }
        else               { CP_WAIT0(); }
        __syncthreads();
        const uint32_t bufb = smu + (kc & 1) * BUF_B;
        const uint32_t aA0 = bufb + (uint32_t)(wm * 32 + arow) * TROW_B + acolb;
        const uint32_t bB0 = bufb + 2 * TILE_B + (uint32_t)(wn * 64 + brow) * TROW_B + bcolb;
#pragma unroll
        for (int ks = 0; ks < 2; ++ks) {
            uint32_t ah[2][4], al[2][4], bh[4][4], bl[4][4];
#pragma unroll
            for (int mf = 0; mf < 2; ++mf) {
                ldsm_x4(ah[mf], aA0 + mf * 16 * TROW_B + ks * 32);
                ldsm_x4(al[mf], aA0 + TILE_B + mf * 16 * TROW_B + ks * 32);
            }
#pragma unroll
            for (int nfp = 0; nfp < 4; ++nfp) {
                ldsm_x4(bh[nfp], bB0 + nfp * 16 * TROW_B + ks * 32);
                ldsm_x4(bl[nfp], bB0 + TILE_B + nfp * 16 * TROW_B + ks * 32);
            }
#pragma unroll
            for (int nfp = 0; nfp < 4; ++nfp)
#pragma unroll
                for (int hf = 0; hf < 2; ++hf) {
                    const int nf = nfp * 2 + hf;
                    const uint32_t b0h = bh[nfp][hf * 2], b1h = bh[nfp][hf * 2 + 1];
                    const uint32_t b0l = bl[nfp][hf * 2], b1l = bl[nfp][hf * 2 + 1];
#pragma unroll
                    for (int mf = 0; mf < 2; ++mf) {
                        mma16816(acc[mf][nf], ah[mf][0], ah[mf][1], ah[mf][2], ah[mf][3], b0h, b1h);
                        mma16816(acc[mf][nf], al[mf][0], al[mf][1], al[mf][2], al[mf][3], b0h, b1h);
                        mma16816(acc[mf][nf], ah[mf][0], ah[mf][1], ah[mf][2], ah[mf][3], b0l, b1l);
                    }
                }
        }
        __syncthreads();
    }
#undef ISSUE
}

// ---------------------------------------------------------------------------
// Combined GEMM kernel: z=0 -> h GEMM (+split store, +src/dst logits);
//                       z=1 -> gate GEMM (store sigmoid(acc+Hb)).
// ---------------------------------------------------------------------------
__global__ __launch_bounds__(256) void gemm_all_kernel(const float* __restrict__ wsrc,
                                                       const float* __restrict__ wdst,
                                                       const float* __restrict__ Hb) {
    extern __shared__ char sm[];
    const int m0 = blockIdx.y << 7;
    const int n0 = blockIdx.x << 7;
    float acc[2][8][4];
#pragma unroll
    for (int mf = 0; mf < 2; ++mf)
#pragma unroll
        for (int nf = 0; nf < 8; ++nf)
#pragma unroll
            for (int q = 0; q < 4; ++q) acc[mf][nf][q] = 0.f;

    const int warp = threadIdx.x >> 5, lane = threadIdx.x & 31;
    const int wm = warp & 3, wn = warp >> 2;
    const int g = lane >> 2, t = lane & 3;

    if (blockIdx.z == 0) {
        hmma_mainloop(acc, g_fh, g_fl, g_w1h, g_w1l, m0, n0, sm);
        const int head = (n0 >> 6) + wn;
        float sd[2][2], dd[2][2];
#pragma unroll
        for (int mf = 0; mf < 2; ++mf) sd[mf][0] = sd[mf][1] = dd[mf][0] = dd[mf][1] = 0.f;
#pragma unroll
        for (int mf = 0; mf < 2; ++mf) {
            const int m = m0 + wm * 32 + mf * 16 + g;
            const int b = m >> 9, i = m & (N_ - 1);
            const int ba = b * A_ + head;
#pragma unroll
            for (int nf = 0; nf < 8; ++nf) {
                const int e = nf * 8 + 2 * t;
                __nv_bfloat16 h0, l0, h1, l1;
                split2(acc[mf][nf][0], h0, l0);
                split2(acc[mf][nf][1], h1, l1);
                *(__nv_bfloat162*)&g_hbh[((size_t)(ba * N_ + i)) * E_ + e] = __nv_bfloat162(h0, h1);
                *(__nv_bfloat162*)&g_hbl[((size_t)(ba * N_ + i)) * E_ + e] = __nv_bfloat162(l0, l1);
                split2(acc[mf][nf][2], h0, l0);
                split2(acc[mf][nf][3], h1, l1);
                *(__nv_bfloat162*)&g_hbh[((size_t)(ba * N_ + i + 8)) * E_ + e] = __nv_bfloat162(h0, h1);
                *(__nv_bfloat162*)&g_hbl[((size_t)(ba * N_ + i + 8)) * E_ + e] = __nv_bfloat162(l0, l1);
                float2 ws = *(const float2*)(wsrc + head * E_ + e);
                float2 wd = *(const float2*)(wdst + head * E_ + e);
                float t0 = tanhf(acc[mf][nf][0]), t1 = tanhf(acc[mf][nf][1]);
                float t2 = tanhf(acc[mf][nf][2]), t3 = tanhf(acc[mf][nf][3]);
                sd[mf][0] += t0 * ws.x + t1 * ws.y;
                sd[mf][1] += t2 * ws.x + t3 * ws.y;
                dd[mf][0] += t0 * wd.x + t1 * wd.y;
                dd[mf][1] += t2 * wd.x + t3 * wd.y;
            }
#pragma unroll
            for (int rh = 0; rh < 2; ++rh) {
                float s = sd[mf][rh], d = dd[mf][rh];
                s += __shfl_xor_sync(0xffffffffu, s, 1);
                s += __shfl_xor_sync(0xffffffffu, s, 2);
                d += __shfl_xor_sync(0xffffffffu, d, 1);
                d += __shfl_xor_sync(0xffffffffu, d, 2);
                if (t == 0) {
                    g_src[ba * N_ + i + rh * 8] = s;
                    g_dst[ba * N_ + i + rh * 8] = d;
                }
            }
        }
    } else {
        hmma_mainloop(acc, g_fh, g_fl, g_w2h, g_w2l, m0, n0, sm);
#pragma unroll
        for (int mf = 0; mf < 2; ++mf)
#pragma unroll
            for (int nf = 0; nf < 8; ++nf) {
                const int m = m0 + wm * 32 + mf * 16 + g;
                const int n = n0 + wn * 64 + nf * 8 + 2 * t;
                float2 hb = *(const float2*)(Hb + n);
#pragma unroll
                for (int rr = 0; rr < 2; ++rr) {
                    const int mm = m + rr * 8;
                    float2 gv;
                    gv.x = 1.f / (1.f + __expf(-(acc[mf][nf][rr * 2 + 0] + hb.x)));
                    gv.y = 1.f / (1.f + __expf(-(acc[mf][nf][rr * 2 + 1] + hb.y)));
                    *(float2*)(g_gate + (size_t)mm * D_ + n) = gv;
                }
            }
    }
}

// ---------------------------------------------------------------------------
// Attention (HMMA, i-tile 64, 3 CTAs/SM) + fused highway blend epilogue:
// out = gate*elu(attn_out) + (1-gate)*feat   (written directly to d_out)
// ---------------------------------------------------------------------------
#define IT_ 64
#define HC_ROWB 144
#define HC_BUF_B (64 * HC_ROWB)          // 9216
#define P_ROWB 144
#define OFF_HCH 0
#define OFF_HCL 18432
#define OFF_PBH 36864
#define OFF_PBL 46080
#define OFF_SRC 55296
#define OFF_DST 55552
#define OFF_MS  57600
#define OFF_SUM 61696
#define ATT_SMEM_B 61952

__global__ __launch_bounds__(256, 3) void attn_kernel(const void* __restrict__ adjv,
                                                      const float* __restrict__ bbias,
                                                      const float* __restrict__ feat,
                                                      float* __restrict__ out) {
    extern __shared__ char sm[];
    const uint32_t smu = smem_u32(sm);
    char* Pbh = sm + OFF_PBH;
    char* Pbl = sm + OFF_PBL;
    float* s_src = (float*)(sm + OFF_SRC);
    float* s_dst = (float*)(sm + OFF_DST);
    float* s_sum = (float*)(sm + OFF_SUM);
    unsigned short* Ms = (unsigned short*)(sm + OFF_MS);   // [32 jwords][64 rows]

    const int tid = threadIdx.x;
    const int lane = tid & 31, warp = tid >> 5;
    const int b = blockIdx.z, a = blockIdx.y, it = blockIdx.x;
    const int ba = b * A_ + a;
    const int i0 = it * IT_;

    const __nv_bfloat16* srcH = g_hbh + (size_t)ba * N_ * E_;
    const __nv_bfloat16* srcL = g_hbl + (size_t)ba * N_ * E_;

#define ISSUE_H(jc, buf) do {                                                \
    const int _j0 = (jc) * 64;                                               \
    _Pragma("unroll")                                                        \
    for (int _c = 0; _c < 2; ++_c) {                                         \
        const int _idx = tid * 2 + _c;                                       \
        const int _jr = _idx >> 3, _q = _idx & 7;                            \
        const uint32_t _dst = smu + OFF_HCH + (buf) * HC_BUF_B + _jr * HC_ROWB + _q * 16; \
        CP16(_dst, srcH + (size_t)(_j0 + _jr) * E_ + _q * 8);                \
        CP16(_dst + (OFF_HCL - OFF_HCH), srcL + (size_t)(_j0 + _jr) * E_ + _q * 8); \
    }                                                                        \
    CP_COMMIT(); } while (0)

    // ---- Phase A ----
    ISSUE_H(0, 0);
    if (tid < IT_) s_src[tid] = g_src[ba * N_ + i0 + tid];
    s_dst[tid] = g_dst[ba * N_ + tid];
    s_dst[tid + 256] = g_dst[ba * N_ + tid + 256];
    __syncthreads();

    // ---- Phase B: mask bits ----
    const int adj_int = g_adj_int;
    for (int rr = warp; rr < IT_; rr += 8) {
        const size_t rowoff = (size_t)(b * N_ + i0 + rr) * N_;
        unsigned mbits = 0;
        if (adj_int) {
            const uint4* ap = (const uint4*)((const int*)adjv + rowoff + lane * 16);
#pragma unroll
            for (int q = 0; q < 4; ++q) {
                uint4 w = ap[q];
                mbits |= (w.x ? 1u : 0u) << (q * 4 + 0);
                mbits |= (w.y ? 1u : 0u) << (q * 4 + 1);
                mbits |= (w.z ? 1u : 0u) << (q * 4 + 2);
                mbits |= (w.w ? 1u : 0u) << (q * 4 + 3);
            }
        } else {
            uint4 w = *(const uint4*)((const uint8_t*)adjv + rowoff + lane * 16);
            unsigned ws[4] = {w.x, w.y, w.z, w.w};
#pragma unroll
            for (int q = 0; q < 4; ++q)
#pragma unroll
                for (int bq = 0; bq < 4; ++bq)
                    mbits |= (((ws[q] >> (8 * bq)) & 0xffu) ? 1u : 0u) << (q * 4 + bq);
        }
        Ms[lane * IT_ + rr] = (unsigned short)mbits;
    }
    __syncthreads();

    // ---- Phase C ----
    const int wm = warp & 1, wn = warp >> 1;
    const int r = tid >> 2, jseg = (tid & 3) * 16;
    const float srcv = s_src[r];

    const int arow = (lane & 7) + ((lane >> 3) & 1) * 8;
    const int acolb = (lane >> 4) * 16;
    const uint32_t aP0 = smu + OFF_PBH + (uint32_t)(wm * 32 + arow) * P_ROWB + acolb;
    const int jrow = lane & 15;
    const int ecolb = (lane >> 4) * 16;
    const uint32_t bH0 = smu + OFF_HCH + (uint32_t)jrow * HC_ROWB + (wn * 16) * 2 + ecolb;

    float acc[2][2][4];
#pragma unroll
    for (int mf = 0; mf < 2; ++mf)
#pragma unroll
        for (int nf = 0; nf < 2; ++nf)
#pragma unroll
            for (int q = 0; q < 4; ++q) acc[mf][nf][q] = 0.f;

    float psum = 0.f;

    for (int jc = 0; jc < 8; ++jc) {
        {
            const int jb = jc * 64 + jseg;
            uint32_t mbits = Ms[(jb >> 4) * IT_ + r];
#pragma unroll
            for (int q = 0; q < 16; q += 4) {
                float4 dv = *(const float4*)&s_dst[jb + q];
                float p[4];
#pragma unroll
                for (int e = 0; e < 4; ++e) {
                    float v = srcv + (&dv.x)[e];
                    v = v >= 0.f ? v : 0.2f * v;
                    p[e] = ((mbits >> (q + e)) & 1u) ? __expf(v) : 0.f;
                    psum += p[e];
                }
                __nv_bfloat16 h0, l0, h1, l1;
                split2(p[0], h0, l0); split2(p[1], h1, l1);
                *(__nv_bfloat162*)(Pbh + r * P_ROWB + (jseg + q) * 2) = __nv_bfloat162(h0, h1);
                *(__nv_bfloat162*)(Pbl + r * P_ROWB + (jseg + q) * 2) = __nv_bfloat162(l0, l1);
                split2(p[2], h0, l0); split2(p[3], h1, l1);
                *(__nv_bfloat162*)(Pbh + r * P_ROWB + (jseg + q + 2) * 2) = __nv_bfloat162(h0, h1);
                *(__nv_bfloat162*)(Pbl + r * P_ROWB + (jseg + q + 2) * 2) = __nv_bfloat162(l0, l1);
            }
        }
        if (jc + 1 < 8) { ISSUE_H(jc + 1, (jc + 1) & 1); CP_WAIT1(); }
        else            { CP_WAIT0(); }
        __syncthreads();

        const uint32_t bbuf = bH0 + (jc & 1) * HC_BUF_B;
#pragma unroll
        for (int ks = 0; ks < 4; ++ks) {
            uint32_t ah[2][4], al[2][4], bh[4], bl[4];
#pragma unroll
            for (int mf = 0; mf < 2; ++mf) {
                ldsm_x4(ah[mf], aP0 + mf * 16 * P_ROWB + ks * 32);
                ldsm_x4(al[mf], aP0 + (OFF_PBL - OFF_PBH) + mf * 16 * P_ROWB + ks * 32);
            }
            const uint32_t bbase = bbuf + (uint32_t)(ks * 16) * HC_ROWB;
            ldsm_x4_t(bh, bbase);
            ldsm_x4_t(bl, bbase + (OFF_HCL - OFF_HCH));
#pragma unroll
            for (int nf = 0; nf < 2; ++nf) {
                const uint32_t b0h = bh[nf * 2], b1h = bh[nf * 2 + 1];
                const uint32_t b0l = bl[nf * 2], b1l = bl[nf * 2 + 1];
#pragma unroll
                for (int mf = 0; mf < 2; ++mf) {
                    mma16816(acc[mf][nf], ah[mf][0], ah[mf][1], ah[mf][2], ah[mf][3], b0h, b1h);
                    mma16816(acc[mf][nf], al[mf][0], al[mf][1], al[mf][2], al[mf][3], b0h, b1h);
                    mma16816(acc[mf][nf], ah[mf][0], ah[mf][1], ah[mf][2], ah[mf][3], b0l, b1l);
                }
            }
        }
        __syncthreads();
    }
#undef ISSUE_H

    // row-sum: quad-reduce and publish
    psum += __shfl_xor_sync(0xffffffffu, psum, 1);
    psum += __shfl_xor_sync(0xffffffffu, psum, 2);
    if ((tid & 3) == 0) s_sum[r] = psum;
    __syncthreads();

    // ---- epilogue: normalize + bias + elu + highway blend -> d_out ----
    const int g = lane >> 2, t = lane & 3;
#pragma unroll
    for (int mf = 0; mf < 2; ++mf) {
        const int rl = wm * 32 + mf * 16 + g;
        const float inv0 = __fdividef(1.f, s_sum[rl]);
        const float inv1 = __fdividef(1.f, s_sum[rl + 8]);
#pragma unroll
        for (int nf = 0; nf < 2; ++nf) {
            const int col = wn * 16 + nf * 8 + 2 * t;
            const int n = a * E_ + col;
            float2 bias = *(const float2*)(bbias + col);
#pragma unroll
            for (int rr = 0; rr < 2; ++rr) {
                const int row = i0 + rl + rr * 8;
                const size_t off = (size_t)(b * N_ + row) * D_ + n;
                const float inv = rr ? inv1 : inv0;
                float2 gv = *(const float2*)(g_gate + off);
                float2 fv = *(const float2*)(feat + off);
                float a0 = fmaf(acc[mf][nf][rr * 2 + 0], inv, bias.x);
                float a1 = fmaf(acc[mf][nf][rr * 2 + 1], inv, bias.y);
                float fo0 = a0 > 0.f ? a0 : (__expf(a0) - 1.f);
                float fo1 = a1 > 0.f ? a1 : (__expf(a1) - 1.f);
                float2 ov;
                ov.x = gv.x * fo0 + (1.f - gv.x) * fv.x;
                ov.y = gv.y * fo1 + (1.f - gv.y) * fv.y;
                *(float2*)(out + off) = ov;
            }
        }
    }
}

// ---------------------------------------------------------------------------
extern "C" void kernel_launch(void* const* d_in, const int* in_sizes, int n_in,
                              void* d_out, int out_size) {
    const float* feat = (const float*)d_in[0];
    const void* adj = d_in[1];
    const float* W = (const float*)d_in[2];
    const float* bbias = (const float*)d_in[3];
    const float* wsrc = (const float*)d_in[4];
    const float* wdst = (const float*)d_in[5];
    const float* Hw = (const float*)d_in[6];
    const float* Hb = (const float*)d_in[7];
    float* out = (float*)d_out;

    prep_kernel<<<PREP_GRID, 256>>>(feat, W, Hw, (const int*)adj);

    cudaFuncSetAttribute(gemm_all_kernel, cudaFuncAttributeMaxDynamicSharedMemorySize, GEMM_SMEM);
    cudaFuncSetAttribute(attn_kernel, cudaFuncAttributeMaxDynamicSharedMemorySize, ATT_SMEM_B);

    gemm_all_kernel<<<dim3(D_ / 128, M_ / 128, 2), 256, GEMM_SMEM>>>(wsrc, wdst, Hb);

    attn_kernel<<<dim3(N_ / IT_, A_, B_), 256, ATT_SMEM_B>>>(adj, bbias, feat, out);
}

// round 14
// speedup vs baseline: 1.5579x; 1.1434x over previous
#include <cuda_runtime.h>
#include <cuda_bf16.h>
#include <stdint.h>

// Problem constants
#define B_ 8
#define N_ 512
#define D_ 768
#define A_ 12
#define E_ 64
#define M_ (B_ * N_)   // 4096

// ---------------------------------------------------------------------------
// PTX helpers (all baseline features: valid for compute_103 virtual arch)
// ---------------------------------------------------------------------------
__device__ __forceinline__ uint32_t smem_u32(const void* p) {
    uint32_t a;
    asm("{ .reg .u64 t; cvta.to.shared.u64 t, %1; cvt.u32.u64 %0, t; }" : "=r"(a) : "l"(p));
    return a;
}
__device__ __forceinline__ void ldsm_x4(uint32_t* r, uint32_t addr) {
    asm volatile("ldmatrix.sync.aligned.m8n8.x4.shared.b16 {%0,%1,%2,%3}, [%4];"
        : "=r"(r[0]), "=r"(r[1]), "=r"(r[2]), "=r"(r[3]) : "r"(addr));
}
__device__ __forceinline__ void ldsm_x4_t(uint32_t* r, uint32_t addr) {
    asm volatile("ldmatrix.sync.aligned.m8n8.x4.trans.shared.b16 {%0,%1,%2,%3}, [%4];"
        : "=r"(r[0]), "=r"(r[1]), "=r"(r[2]), "=r"(r[3]) : "r"(addr));
}
#define CP16(dst, src) asm volatile("cp.async.cg.shared.global [%0], [%1], 16;" :: "r"(dst), "l"(src))
#define CP_COMMIT() asm volatile("cp.async.commit_group;" ::: "memory")
#define CP_WAIT1() asm volatile("cp.async.wait_group 1;" ::: "memory")
#define CP_WAIT0() asm volatile("cp.async.wait_group 0;" ::: "memory")

__device__ __forceinline__ void mma16816(float* c,
        uint32_t a0, uint32_t a1, uint32_t a2, uint32_t a3,
        uint32_t b0, uint32_t b1) {
    asm volatile(
        "mma.sync.aligned.m16n8k16.row.col.f32.bf16.bf16.f32 "
        "{%0,%1,%2,%3}, {%4,%5,%6,%7}, {%8,%9}, {%0,%1,%2,%3};"
        : "+f"(c[0]), "+f"(c[1]), "+f"(c[2]), "+f"(c[3])
        : "r"(a0), "r"(a1), "r"(a2), "r"(a3), "r"(b0), "r"(b1));
}

// ---------------------------------------------------------------------------
// Scratch (device globals: allocation-free)
// ---------------------------------------------------------------------------
__device__ float g_src[B_ * A_ * N_];
__device__ float g_dst[B_ * A_ * N_];
__device__ float g_gate[B_ * N_ * D_];       // sigmoid(feat @ Hw^T + Hb)
__device__ int   g_adj_int;
// h in bf16 hi/lo, layout [ba][j][e]
__device__ __align__(16) __nv_bfloat16 g_hbh[B_ * A_ * N_ * E_];
__device__ __align__(16) __nv_bfloat16 g_hbl[B_ * A_ * N_ * E_];
// bf16 split GEMM operands (hi + lo)
__device__ __align__(16) __nv_bfloat16 g_fh[M_ * D_];
__device__ __align__(16) __nv_bfloat16 g_fl[M_ * D_];
__device__ __align__(16) __nv_bfloat16 g_w1h[D_ * D_];  // W^T: row n=a*64+e, col k=d
__device__ __align__(16) __nv_bfloat16 g_w1l[D_ * D_];
__device__ __align__(16) __nv_bfloat16 g_w2h[D_ * D_];  // Hw: row n, col k=d

// ---------------------------------------------------------------------------
// fp32 -> bf16 hi/lo split
// ---------------------------------------------------------------------------
__device__ __forceinline__ void split2(float x, __nv_bfloat16& h, __nv_bfloat16& l) {
    h = __float2bfloat16(x);
    l = __float2bfloat16(x - __bfloat162float(h));
}

// ---------------------------------------------------------------------------
// Combined prep kernel: feat conv | w2 conv (hi only) | w1 conv | adj detect
// ---------------------------------------------------------------------------
#define PREP_FEAT 3072
#define PREP_W2 (PREP_FEAT + 576)
#define PREP_W1 (PREP_W2 + 144)
#define PREP_GRID (PREP_W1 + 1)

__global__ void prep_kernel(const float* __restrict__ f, const float* __restrict__ W,
                            const float* __restrict__ Hw, const int* __restrict__ adj) {
    __shared__ float tile[64][65];
    const int bx = blockIdx.x;
    const int tid = threadIdx.x;
    if (bx < PREP_FEAT) {
        const int g4 = (bx * 256 + tid) * 4;
        float4 v = *(const float4*)(f + g4);
        __nv_bfloat16 h0, h1, h2, h3, l0, l1, l2, l3;
        split2(v.x, h0, l0); split2(v.y, h1, l1); split2(v.z, h2, l2); split2(v.w, h3, l3);
        ((__nv_bfloat162*)(g_fh + g4))[0] = __nv_bfloat162(h0, h1);
        ((__nv_bfloat162*)(g_fh + g4))[1] = __nv_bfloat162(h2, h3);
        ((__nv_bfloat162*)(g_fl + g4))[0] = __nv_bfloat162(l0, l1);
        ((__nv_bfloat162*)(g_fl + g4))[1] = __nv_bfloat162(l2, l3);
    } else if (bx < PREP_W2) {
        const int g4 = ((bx - PREP_FEAT) * 256 + tid) * 4;
        float4 v = *(const float4*)(Hw + g4);
        __nv_bfloat16 h0 = __float2bfloat16(v.x), h1 = __float2bfloat16(v.y);
        __nv_bfloat16 h2 = __float2bfloat16(v.z), h3 = __float2bfloat16(v.w);
        ((__nv_bfloat162*)(g_w2h + g4))[0] = __nv_bfloat162(h0, h1);
        ((__nv_bfloat162*)(g_w2h + g4))[1] = __nv_bfloat162(h2, h3);
    } else if (bx < PREP_W1) {
        const int idx0 = bx - PREP_W2;
        const int a = idx0 / (D_ / 64), d0 = (idx0 % (D_ / 64)) * 64;
#pragma unroll
        for (int it = 0; it < 16; ++it) {
            const int idx = it * 256 + tid;
            const int dd = idx >> 6, e = idx & 63;
            tile[dd][e] = W[(a * D_ + d0 + dd) * E_ + e];
        }
        __syncthreads();
#pragma unroll
        for (int it = 0; it < 16; ++it) {
            const int idx = it * 256 + tid;
            const int e = idx >> 6, dd = idx & 63;
            __nv_bfloat16 h, l;
            split2(tile[dd][e], h, l);
            g_w1h[(a * 64 + e) * D_ + d0 + dd] = h;
            g_w1l[(a * 64 + e) * D_ + d0 + dd] = l;
        }
    } else {
        if (tid < 32) {
            int ok = 1;
            for (int v = tid; v < 1024; v += 32) {
                int w = adj[v];
                if (w != 0 && w != 1) ok = 0;
            }
#pragma unroll
            for (int o = 16; o; o >>= 1) ok &= __shfl_xor_sync(0xffffffffu, ok, o);
            if (tid == 0) g_adj_int = ok;
        }
    }
}

// ---------------------------------------------------------------------------
// HMMA bf16 GEMM mainloop: 128x128 block, 8 warps (4m x 2n), warp 32x64.
// USE_BL: include the Ah*Bl term (bf16x3) vs skip Bl entirely (bf16x2).
// ---------------------------------------------------------------------------
#define KC_ 32
#define NKC_ (D_ / KC_)          // 24
#define TROW_B 80
#define TILE_B (128 * TROW_B)    // 10240
#define BUF_B (4 * TILE_B)       // 40960
#define GEMM_SMEM (2 * BUF_B)    // 81920

template <bool USE_BL>
__device__ __forceinline__ void hmma_mainloop(
        float acc[2][8][4],
        const __nv_bfloat16* __restrict__ Ah, const __nv_bfloat16* __restrict__ Al,
        const __nv_bfloat16* __restrict__ Bh, const __nv_bfloat16* __restrict__ Bl,
        int m0, int n0, char* sm) {
    const int tid = threadIdx.x;
    const int warp = tid >> 5, lane = tid & 31;
    const int wm = warp & 3, wn = warp >> 2;

    const int lr = tid >> 1;
    const int lce = (tid & 1) * 16;
    const uint32_t sto = (uint32_t)lr * TROW_B + (tid & 1) * 32;
    const uint32_t smu = smem_u32(sm);

    const __nv_bfloat16* pAh = Ah + (size_t)(m0 + lr) * D_ + lce;
    const __nv_bfloat16* pAl = Al + (size_t)(m0 + lr) * D_ + lce;
    const __nv_bfloat16* pBh = Bh + (size_t)(n0 + lr) * D_ + lce;
    const __nv_bfloat16* pBl = USE_BL ? (Bl + (size_t)(n0 + lr) * D_ + lce) : pBh;

#define ISSUE(kc, buf) do {                                                  \
    uint32_t _bb = smu + (buf) * BUF_B + sto;                                \
    const int _o = (kc) * KC_;                                               \
    CP16(_bb, pAh + _o);                 CP16(_bb + 16, pAh + _o + 8);       \
    CP16(_bb + TILE_B, pAl + _o);        CP16(_bb + TILE_B + 16, pAl + _o + 8); \
    CP16(_bb + 2 * TILE_B, pBh + _o);    CP16(_bb + 2 * TILE_B + 16, pBh + _o + 8); \
    if (USE_BL) {                                                            \
        CP16(_bb + 3 * TILE_B, pBl + _o);                                    \
        CP16(_bb + 3 * TILE_B + 16, pBl + _o + 8);                           \
    }                                                                        \
    CP_COMMIT(); } while (0)

    ISSUE(0, 0);

    const int arow = (lane & 7) + ((lane >> 3) & 1) * 8;
    const int acolb = (lane >> 4) * 16;
    const int brow = (lane & 7) + (lane >> 4) * 8;
    const int bcolb = ((lane >> 3) & 1) * 16;

    for (int kc = 0; kc < NKC_; ++kc) {
        if (kc + 1 < NKC_) { ISSUE(kc + 1, (kc + 1) & 1); CP_WAIT1(); }
        else               { CP_WAIT0(); }
        __syncthreads();
        const uint32_t bufb = smu + (kc & 1) * BUF_B;
        const uint32_t aA0 = bufb + (uint32_t)(wm * 32 + arow) * TROW_B + acolb;
        const uint32_t bB0 = bufb + 2 * TILE_B + (uint32_t)(wn * 64 + brow) * TROW_B + bcolb;
#pragma unroll
        for (int ks = 0; ks < 2; ++ks) {
            uint32_t ah[2][4], al[2][4], bh[4][4], bl[4][4];
#pragma unroll
            for (int mf = 0; mf < 2; ++mf) {
                ldsm_x4(ah[mf], aA0 + mf * 16 * TROW_B + ks * 32);
                ldsm_x4(al[mf], aA0 + TILE_B + mf * 16 * TROW_B + ks * 32);
            }
#pragma unroll
            for (int nfp = 0; nfp < 4; ++nfp) {
                ldsm_x4(bh[nfp], bB0 + nfp * 16 * TROW_B + ks * 32);
                if (USE_BL) ldsm_x4(bl[nfp], bB0 + TILE_B + nfp * 16 * TROW_B + ks * 32);
            }
#pragma unroll
            for (int nfp = 0; nfp < 4; ++nfp)
#pragma unroll
                for (int hf = 0; hf < 2; ++hf) {
                    const int nf = nfp * 2 + hf;
                    const uint32_t b0h = bh[nfp][hf * 2], b1h = bh[nfp][hf * 2 + 1];
#pragma unroll
                    for (int mf = 0; mf < 2; ++mf) {
                        mma16816(acc[mf][nf], ah[mf][0], ah[mf][1], ah[mf][2], ah[mf][3], b0h, b1h);
                        mma16816(acc[mf][nf], al[mf][0], al[mf][1], al[mf][2], al[mf][3], b0h, b1h);
                        if (USE_BL)
                            mma16816(acc[mf][nf], ah[mf][0], ah[mf][1], ah[mf][2], ah[mf][3],
                                     bl[nfp][hf * 2], bl[nfp][hf * 2 + 1]);
                    }
                }
        }
        __syncthreads();
    }
#undef ISSUE
}

// ---------------------------------------------------------------------------
// Combined GEMM kernel: z=0 -> h GEMM (bf16x3, split store + src/dst logits);
//                       z=1 -> gate GEMM (bf16x2, store sigmoid(acc+Hb)).
// ---------------------------------------------------------------------------
__global__ __launch_bounds__(256, 2) void gemm_all_kernel(const float* __restrict__ wsrc,
                                                          const float* __restrict__ wdst,
                                                          const float* __restrict__ Hb) {
    extern __shared__ char sm[];
    const int m0 = blockIdx.y << 7;
    const int n0 = blockIdx.x << 7;
    float acc[2][8][4];
#pragma unroll
    for (int mf = 0; mf < 2; ++mf)
#pragma unroll
        for (int nf = 0; nf < 8; ++nf)
#pragma unroll
            for (int q = 0; q < 4; ++q) acc[mf][nf][q] = 0.f;

    const int warp = threadIdx.x >> 5, lane = threadIdx.x & 31;
    const int wm = warp & 3, wn = warp >> 2;
    const int g = lane >> 2, t = lane & 3;

    if (blockIdx.z == 0) {
        hmma_mainloop<true>(acc, g_fh, g_fl, g_w1h, g_w1l, m0, n0, sm);
        const int head = (n0 >> 6) + wn;
        float sd[2][2], dd[2][2];
#pragma unroll
        for (int mf = 0; mf < 2; ++mf) sd[mf][0] = sd[mf][1] = dd[mf][0] = dd[mf][1] = 0.f;
#pragma unroll
        for (int mf = 0; mf < 2; ++mf) {
            const int m = m0 + wm * 32 + mf * 16 + g;
            const int b = m >> 9, i = m & (N_ - 1);
            const int ba = b * A_ + head;
#pragma unroll
            for (int nf = 0; nf < 8; ++nf) {
                const int e = nf * 8 + 2 * t;
                __nv_bfloat16 h0, l0, h1, l1;
                split2(acc[mf][nf][0], h0, l0);
                split2(acc[mf][nf][1], h1, l1);
                *(__nv_bfloat162*)&g_hbh[((size_t)(ba * N_ + i)) * E_ + e] = __nv_bfloat162(h0, h1);
                *(__nv_bfloat162*)&g_hbl[((size_t)(ba * N_ + i)) * E_ + e] = __nv_bfloat162(l0, l1);
                split2(acc[mf][nf][2], h0, l0);
                split2(acc[mf][nf][3], h1, l1);
                *(__nv_bfloat162*)&g_hbh[((size_t)(ba * N_ + i + 8)) * E_ + e] = __nv_bfloat162(h0, h1);
                *(__nv_bfloat162*)&g_hbl[((size_t)(ba * N_ + i + 8)) * E_ + e] = __nv_bfloat162(l0, l1);
                float2 ws = *(const float2*)(wsrc + head * E_ + e);
                float2 wd = *(const float2*)(wdst + head * E_ + e);
                float t0 = tanhf(acc[mf][nf][0]), t1 = tanhf(acc[mf][nf][1]);
                float t2 = tanhf(acc[mf][nf][2]), t3 = tanhf(acc[mf][nf][3]);
                sd[mf][0] += t0 * ws.x + t1 * ws.y;
                sd[mf][1] += t2 * ws.x + t3 * ws.y;
                dd[mf][0] += t0 * wd.x + t1 * wd.y;
                dd[mf][1] += t2 * wd.x + t3 * wd.y;
            }
#pragma unroll
            for (int rh = 0; rh < 2; ++rh) {
                float s = sd[mf][rh], d = dd[mf][rh];
                s += __shfl_xor_sync(0xffffffffu, s, 1);
                s += __shfl_xor_sync(0xffffffffu, s, 2);
                d += __shfl_xor_sync(0xffffffffu, d, 1);
                d += __shfl_xor_sync(0xffffffffu, d, 2);
                if (t == 0) {
                    g_src[ba * N_ + i + rh * 8] = s;
                    g_dst[ba * N_ + i + rh * 8] = d;
                }
            }
        }
    } else {
        hmma_mainloop<false>(acc, g_fh, g_fl, g_w2h, g_w2h, m0, n0, sm);
#pragma unroll
        for (int mf = 0; mf < 2; ++mf)
#pragma unroll
            for (int nf = 0; nf < 8; ++nf) {
                const int m = m0 + wm * 32 + mf * 16 + g;
                const int n = n0 + wn * 64 + nf * 8 + 2 * t;
                float2 hb = *(const float2*)(Hb + n);
#pragma unroll
                for (int rr = 0; rr < 2; ++rr) {
                    const int mm = m + rr * 8;
                    float2 gv;
                    gv.x = 1.f / (1.f + __expf(-(acc[mf][nf][rr * 2 + 0] + hb.x)));
                    gv.y = 1.f / (1.f + __expf(-(acc[mf][nf][rr * 2 + 1] + hb.y)));
                    *(float2*)(g_gate + (size_t)mm * D_ + n) = gv;
                }
            }
    }
}

// ---------------------------------------------------------------------------
// Attention (HMMA, i-tile 64, 3 CTAs/SM) + fused highway blend epilogue:
// out = gate*elu(attn_out) + (1-gate)*feat   (written directly to d_out)
// ---------------------------------------------------------------------------
#define IT_ 64
#define HC_ROWB 144
#define HC_BUF_B (64 * HC_ROWB)          // 9216
#define P_ROWB 144
#define OFF_HCH 0
#define OFF_HCL 18432
#define OFF_PBH 36864
#define OFF_PBL 46080
#define OFF_SRC 55296
#define OFF_DST 55552
#define OFF_MS  57600
#define OFF_SUM 61696
#define ATT_SMEM_B 61952

__global__ __launch_bounds__(256, 3) void attn_kernel(const void* __restrict__ adjv,
                                                      const float* __restrict__ bbias,
                                                      const float* __restrict__ feat,
                                                      float* __restrict__ out) {
    extern __shared__ char sm[];
    const uint32_t smu = smem_u32(sm);
    char* Pbh = sm + OFF_PBH;
    char* Pbl = sm + OFF_PBL;
    float* s_src = (float*)(sm + OFF_SRC);
    float* s_dst = (float*)(sm + OFF_DST);
    float* s_sum = (float*)(sm + OFF_SUM);
    unsigned short* Ms = (unsigned short*)(sm + OFF_MS);   // [32 jwords][64 rows]

    const int tid = threadIdx.x;
    const int lane = tid & 31, warp = tid >> 5;
    const int b = blockIdx.z, a = blockIdx.y, it = blockIdx.x;
    const int ba = b * A_ + a;
    const int i0 = it * IT_;

    const __nv_bfloat16* srcH = g_hbh + (size_t)ba * N_ * E_;
    const __nv_bfloat16* srcL = g_hbl + (size_t)ba * N_ * E_;

#define ISSUE_H(jc, buf) do {                                                \
    const int _j0 = (jc) * 64;                                               \
    _Pragma("unroll")                                                        \
    for (int _c = 0; _c < 2; ++_c) {                                         \
        const int _idx = tid * 2 + _c;                                       \
        const int _jr = _idx >> 3, _q = _idx & 7;                            \
        const uint32_t _dst = smu + OFF_HCH + (buf) * HC_BUF_B + _jr * HC_ROWB + _q * 16; \
        CP16(_dst, srcH + (size_t)(_j0 + _jr) * E_ + _q * 8);                \
        CP16(_dst + (OFF_HCL - OFF_HCH), srcL + (size_t)(_j0 + _jr) * E_ + _q * 8); \
    }                                                                        \
    CP_COMMIT(); } while (0)

    // ---- Phase A ----
    ISSUE_H(0, 0);
    if (tid < IT_) s_src[tid] = g_src[ba * N_ + i0 + tid];
    s_dst[tid] = g_dst[ba * N_ + tid];
    s_dst[tid + 256] = g_dst[ba * N_ + tid + 256];
    __syncthreads();

    // ---- Phase B: mask bits ----
    const int adj_int = g_adj_int;
    for (int rr = warp; rr < IT_; rr += 8) {
        const size_t rowoff = (size_t)(b * N_ + i0 + rr) * N_;
        unsigned mbits = 0;
        if (adj_int) {
            const uint4* ap = (const uint4*)((const int*)adjv + rowoff + lane * 16);
#pragma unroll
            for (int q = 0; q < 4; ++q) {
                uint4 w = ap[q];
                mbits |= (w.x ? 1u : 0u) << (q * 4 + 0);
                mbits |= (w.y ? 1u : 0u) << (q * 4 + 1);
                mbits |= (w.z ? 1u : 0u) << (q * 4 + 2);
                mbits |= (w.w ? 1u : 0u) << (q * 4 + 3);
            }
        } else {
            uint4 w = *(const uint4*)((const uint8_t*)adjv + rowoff + lane * 16);
            unsigned ws[4] = {w.x, w.y, w.z, w.w};
#pragma unroll
            for (int q = 0; q < 4; ++q)
#pragma unroll
                for (int bq = 0; bq < 4; ++bq)
                    mbits |= (((ws[q] >> (8 * bq)) & 0xffu) ? 1u : 0u) << (q * 4 + bq);
        }
        Ms[lane * IT_ + rr] = (unsigned short)mbits;
    }
    __syncthreads();

    // ---- Phase C ----
    const int wm = warp & 1, wn = warp >> 1;
    const int r = tid >> 2, jseg = (tid & 3) * 16;
    const float srcv = s_src[r];

    const int arow = (lane & 7) + ((lane >> 3) & 1) * 8;
    const int acolb = (lane >> 4) * 16;
    const uint32_t aP0 = smu + OFF_PBH + (uint32_t)(wm * 32 + arow) * P_ROWB + acolb;
    const int jrow = lane & 15;
    const int ecolb = (lane >> 4) * 16;
    const uint32_t bH0 = smu + OFF_HCH + (uint32_t)jrow * HC_ROWB + (wn * 16) * 2 + ecolb;

    float acc[2][2][4];
#pragma unroll
    for (int mf = 0; mf < 2; ++mf)
#pragma unroll
        for (int nf = 0; nf < 2; ++nf)
#pragma unroll
            for (int q = 0; q < 4; ++q) acc[mf][nf][q] = 0.f;

    float psum = 0.f;

    for (int jc = 0; jc < 8; ++jc) {
        {
            const int jb = jc * 64 + jseg;
            uint32_t mbits = Ms[(jb >> 4) * IT_ + r];
#pragma unroll
            for (int q = 0; q < 16; q += 4) {
                float4 dv = *(const float4*)&s_dst[jb + q];
                float p[4];
#pragma unroll
                for (int e = 0; e < 4; ++e) {
                    float v = srcv + (&dv.x)[e];
                    v = v >= 0.f ? v : 0.2f * v;
                    p[e] = ((mbits >> (q + e)) & 1u) ? __expf(v) : 0.f;
                    psum += p[e];
                }
                __nv_bfloat16 h0, l0, h1, l1;
                split2(p[0], h0, l0); split2(p[1], h1, l1);
                *(__nv_bfloat162*)(Pbh + r * P_ROWB + (jseg + q) * 2) = __nv_bfloat162(h0, h1);
                *(__nv_bfloat162*)(Pbl + r * P_ROWB + (jseg + q) * 2) = __nv_bfloat162(l0, l1);
                split2(p[2], h0, l0); split2(p[3], h1, l1);
                *(__nv_bfloat162*)(Pbh + r * P_ROWB + (jseg + q + 2) * 2) = __nv_bfloat162(h0, h1);
                *(__nv_bfloat162*)(Pbl + r * P_ROWB + (jseg + q + 2) * 2) = __nv_bfloat162(l0, l1);
            }
        }
        if (jc + 1 < 8) { ISSUE_H(jc + 1, (jc + 1) & 1); CP_WAIT1(); }
        else            { CP_WAIT0(); }
        __syncthreads();

        const uint32_t bbuf = bH0 + (jc & 1) * HC_BUF_B;
#pragma unroll
        for (int ks = 0; ks < 4; ++ks) {
            uint32_t ah[2][4], al[2][4], bh[4], bl[4];
#pragma unroll
            for (int mf = 0; mf < 2; ++mf) {
                ldsm_x4(ah[mf], aP0 + mf * 16 * P_ROWB + ks * 32);
                ldsm_x4(al[mf], aP0 + (OFF_PBL - OFF_PBH) + mf * 16 * P_ROWB + ks * 32);
            }
            const uint32_t bbase = bbuf + (uint32_t)(ks * 16) * HC_ROWB;
            ldsm_x4_t(bh, bbase);
            ldsm_x4_t(bl, bbase + (OFF_HCL - OFF_HCH));
#pragma unroll
            for (int nf = 0; nf < 2; ++nf) {
                const uint32_t b0h = bh[nf * 2], b1h = bh[nf * 2 + 1];
                const uint32_t b0l = bl[nf * 2], b1l = bl[nf * 2 + 1];
#pragma unroll
                for (int mf = 0; mf < 2; ++mf) {
                    mma16816(acc[mf][nf], ah[mf][0], ah[mf][1], ah[mf][2], ah[mf][3], b0h, b1h);
                    mma16816(acc[mf][nf], al[mf][0], al[mf][1], al[mf][2], al[mf][3], b0h, b1h);
                    mma16816(acc[mf][nf], ah[mf][0], ah[mf][1], ah[mf][2], ah[mf][3], b0l, b1l);
                }
            }
        }
        __syncthreads();
    }
#undef ISSUE_H

    // row-sum: quad-reduce and publish
    psum += __shfl_xor_sync(0xffffffffu, psum, 1);
    psum += __shfl_xor_sync(0xffffffffu, psum, 2);
    if ((tid & 3) == 0) s_sum[r] = psum;
    __syncthreads();

    // ---- epilogue: normalize + bias + elu + highway blend -> d_out ----
    const int g = lane >> 2, t = lane & 3;
#pragma unroll
    for (int mf = 0; mf < 2; ++mf) {
        const int rl = wm * 32 + mf * 16 + g;
        const float inv0 = __fdividef(1.f, s_sum[rl]);
        const float inv1 = __fdividef(1.f, s_sum[rl + 8]);
#pragma unroll
        for (int nf = 0; nf < 2; ++nf) {
            const int col = wn * 16 + nf * 8 + 2 * t;
            const int n = a * E_ + col;
            float2 bias = *(const float2*)(bbias + col);
#pragma unroll
            for (int rr = 0; rr < 2; ++rr) {
                const int row = i0 + rl + rr * 8;
                const size_t off = (size_t)(b * N_ + row) * D_ + n;
                const float inv = rr ? inv1 : inv0;
                float2 gv = *(const float2*)(g_gate + off);
                float2 fv = *(const float2*)(feat + off);
                float a0 = fmaf(acc[mf][nf][rr * 2 + 0], inv, bias.x);
                float a1 = fmaf(acc[mf][nf][rr * 2 + 1], inv, bias.y);
                float fo0 = a0 > 0.f ? a0 : (__expf(a0) - 1.f);
                float fo1 = a1 > 0.f ? a1 : (__expf(a1) - 1.f);
                float2 ov;
                ov.x = gv.x * fo0 + (1.f - gv.x) * fv.x;
                ov.y = gv.y * fo1 + (1.f - gv.y) * fv.y;
                *(float2*)(out + off) = ov;
            }
        }
    }
}

// ---------------------------------------------------------------------------
extern "C" void kernel_launch(void* const* d_in, const int* in_sizes, int n_in,
                              void* d_out, int out_size) {
    const float* feat = (const float*)d_in[0];
    const void* adj = d_in[1];
    const float* W = (const float*)d_in[2];
    const float* bbias = (const float*)d_in[3];
    const float* wsrc = (const float*)d_in[4];
    const float* wdst = (const float*)d_in[5];
    const float* Hw = (const float*)d_in[6];
    const float* Hb = (const float*)d_in[7];
    float* out = (float*)d_out;

    prep_kernel<<<PREP_GRID, 256>>>(feat, W, Hw, (const int*)adj);

    cudaFuncSetAttribute(gemm_all_kernel, cudaFuncAttributeMaxDynamicSharedMemorySize, GEMM_SMEM);
    cudaFuncSetAttribute(attn_kernel, cudaFuncAttributeMaxDynamicSharedMemorySize, ATT_SMEM_B);

    gemm_all_kernel<<<dim3(D_ / 128, M_ / 128, 2), 256, GEMM_SMEM>>>(wsrc, wdst, Hb);

    attn_kernel<<<dim3(N_ / IT_, A_, B_), 256, ATT_SMEM_B>>>(adj, bbias, feat, out);
}

// round 15
// speedup vs baseline: 1.6548x; 1.0622x over previous
#include <cuda_runtime.h>
#include <cuda_bf16.h>
#include <stdint.h>

// Problem constants
#define B_ 8
#define N_ 512
#define D_ 768
#define A_ 12
#define E_ 64
#define M_ (B_ * N_)   // 4096

// ---------------------------------------------------------------------------
// PTX helpers (all baseline features: valid for compute_103 virtual arch)
// ---------------------------------------------------------------------------
__device__ __forceinline__ uint32_t smem_u32(const void* p) {
    uint32_t a;
    asm("{ .reg .u64 t; cvta.to.shared.u64 t, %1; cvt.u32.u64 %0, t; }" : "=r"(a) : "l"(p));
    return a;
}
__device__ __forceinline__ void ldsm_x4(uint32_t* r, uint32_t addr) {
    asm volatile("ldmatrix.sync.aligned.m8n8.x4.shared.b16 {%0,%1,%2,%3}, [%4];"
        : "=r"(r[0]), "=r"(r[1]), "=r"(r[2]), "=r"(r[3]) : "r"(addr));
}
__device__ __forceinline__ void ldsm_x4_t(uint32_t* r, uint32_t addr) {
    asm volatile("ldmatrix.sync.aligned.m8n8.x4.trans.shared.b16 {%0,%1,%2,%3}, [%4];"
        : "=r"(r[0]), "=r"(r[1]), "=r"(r[2]), "=r"(r[3]) : "r"(addr));
}
#define CP16(dst, src) asm volatile("cp.async.cg.shared.global [%0], [%1], 16;" :: "r"(dst), "l"(src))
#define CP_COMMIT() asm volatile("cp.async.commit_group;" ::: "memory")
#define CP_WAIT1() asm volatile("cp.async.wait_group 1;" ::: "memory")
#define CP_WAIT0() asm volatile("cp.async.wait_group 0;" ::: "memory")

__device__ __forceinline__ void mma16816(float* c,
        uint32_t a0, uint32_t a1, uint32_t a2, uint32_t a3,
        uint32_t b0, uint32_t b1) {
    asm volatile(
        "mma.sync.aligned.m16n8k16.row.col.f32.bf16.bf16.f32 "
        "{%0,%1,%2,%3}, {%4,%5,%6,%7}, {%8,%9}, {%0,%1,%2,%3};"
        : "+f"(c[0]), "+f"(c[1]), "+f"(c[2]), "+f"(c[3])
        : "r"(a0), "r"(a1), "r"(a2), "r"(a3), "r"(b0), "r"(b1));
}

// ---------------------------------------------------------------------------
// Scratch (device globals: allocation-free)
// ---------------------------------------------------------------------------
__device__ float g_src[B_ * A_ * N_];
__device__ float g_dst[B_ * A_ * N_];
__device__ float g_gate[B_ * N_ * D_];       // sigmoid(feat @ Hw^T + Hb)
__device__ int   g_adj_int;
// h in bf16 hi/lo, layout [ba][j][e]
__device__ __align__(16) __nv_bfloat16 g_hbh[B_ * A_ * N_ * E_];
__device__ __align__(16) __nv_bfloat16 g_hbl[B_ * A_ * N_ * E_];
// bf16 split GEMM operands (hi + lo)
__device__ __align__(16) __nv_bfloat16 g_fh[M_ * D_];
__device__ __align__(16) __nv_bfloat16 g_fl[M_ * D_];
__device__ __align__(16) __nv_bfloat16 g_w1h[D_ * D_];  // W^T: row n=a*64+e, col k=d
__device__ __align__(16) __nv_bfloat16 g_w1l[D_ * D_];
__device__ __align__(16) __nv_bfloat16 g_w2h[D_ * D_];  // Hw: row n, col k=d

// ---------------------------------------------------------------------------
// fp32 -> bf16 hi/lo split
// ---------------------------------------------------------------------------
__device__ __forceinline__ void split2(float x, __nv_bfloat16& h, __nv_bfloat16& l) {
    h = __float2bfloat16(x);
    l = __float2bfloat16(x - __bfloat162float(h));
}

// ---------------------------------------------------------------------------
// Combined prep kernel: feat conv | w2 conv (hi only) | w1 conv | adj detect
// ---------------------------------------------------------------------------
#define PREP_FEAT 3072
#define PREP_W2 (PREP_FEAT + 576)
#define PREP_W1 (PREP_W2 + 144)
#define PREP_GRID (PREP_W1 + 1)

__global__ void prep_kernel(const float* __restrict__ f, const float* __restrict__ W,
                            const float* __restrict__ Hw, const int* __restrict__ adj) {
    __shared__ float tile[64][65];
    const int bx = blockIdx.x;
    const int tid = threadIdx.x;
    if (bx < PREP_FEAT) {
        const int g4 = (bx * 256 + tid) * 4;
        float4 v = *(const float4*)(f + g4);
        __nv_bfloat16 h0, h1, h2, h3, l0, l1, l2, l3;
        split2(v.x, h0, l0); split2(v.y, h1, l1); split2(v.z, h2, l2); split2(v.w, h3, l3);
        ((__nv_bfloat162*)(g_fh + g4))[0] = __nv_bfloat162(h0, h1);
        ((__nv_bfloat162*)(g_fh + g4))[1] = __nv_bfloat162(h2, h3);
        ((__nv_bfloat162*)(g_fl + g4))[0] = __nv_bfloat162(l0, l1);
        ((__nv_bfloat162*)(g_fl + g4))[1] = __nv_bfloat162(l2, l3);
    } else if (bx < PREP_W2) {
        const int g4 = ((bx - PREP_FEAT) * 256 + tid) * 4;
        float4 v = *(const float4*)(Hw + g4);
        __nv_bfloat16 h0 = __float2bfloat16(v.x), h1 = __float2bfloat16(v.y);
        __nv_bfloat16 h2 = __float2bfloat16(v.z), h3 = __float2bfloat16(v.w);
        ((__nv_bfloat162*)(g_w2h + g4))[0] = __nv_bfloat162(h0, h1);
        ((__nv_bfloat162*)(g_w2h + g4))[1] = __nv_bfloat162(h2, h3);
    } else if (bx < PREP_W1) {
        const int idx0 = bx - PREP_W2;
        const int a = idx0 / (D_ / 64), d0 = (idx0 % (D_ / 64)) * 64;
#pragma unroll
        for (int it = 0; it < 16; ++it) {
            const int idx = it * 256 + tid;
            const int dd = idx >> 6, e = idx & 63;
            tile[dd][e] = W[(a * D_ + d0 + dd) * E_ + e];
        }
        __syncthreads();
#pragma unroll
        for (int it = 0; it < 16; ++it) {
            const int idx = it * 256 + tid;
            const int e = idx >> 6, dd = idx & 63;
            __nv_bfloat16 h, l;
            split2(tile[dd][e], h, l);
            g_w1h[(a * 64 + e) * D_ + d0 + dd] = h;
            g_w1l[(a * 64 + e) * D_ + d0 + dd] = l;
        }
    } else {
        if (tid < 32) {
            int ok = 1;
            for (int v = tid; v < 1024; v += 32) {
                int w = adj[v];
                if (w != 0 && w != 1) ok = 0;
            }
#pragma unroll
            for (int o = 16; o; o >>= 1) ok &= __shfl_xor_sync(0xffffffffu, ok, o);
            if (tid == 0) g_adj_int = ok;
        }
    }
}

// ---------------------------------------------------------------------------
// HMMA bf16 GEMM mainloop: 128x128 block, 8 warps (4m x 2n), warp 32x64.
// Single __syncthreads per k-chunk: wait cp -> sync -> ldsm(ks0) -> issue
// next chunk -> mma; reads hit buf kc&1, writes hit (kc+1)&1, and the
// top-of-loop sync orders stragglers' previous reads before the new writes.
// ---------------------------------------------------------------------------
#define KC_ 32
#define NKC_ (D_ / KC_)          // 24
#define TROW_B 80
#define TILE_B (128 * TROW_B)    // 10240
#define BUF_B (4 * TILE_B)       // 40960
#define GEMM_SMEM (2 * BUF_B)    // 81920

template <bool USE_BL>
__device__ __forceinline__ void hmma_mainloop(
        float acc[2][8][4],
        const __nv_bfloat16* __restrict__ Ah, const __nv_bfloat16* __restrict__ Al,
        const __nv_bfloat16* __restrict__ Bh, const __nv_bfloat16* __restrict__ Bl,
        int m0, int n0, char* sm) {
    const int tid = threadIdx.x;
    const int warp = tid >> 5, lane = tid & 31;
    const int wm = warp & 3, wn = warp >> 2;

    const int lr = tid >> 1;
    const int lce = (tid & 1) * 16;
    const uint32_t sto = (uint32_t)lr * TROW_B + (tid & 1) * 32;
    const uint32_t smu = smem_u32(sm);

    const __nv_bfloat16* pAh = Ah + (size_t)(m0 + lr) * D_ + lce;
    const __nv_bfloat16* pAl = Al + (size_t)(m0 + lr) * D_ + lce;
    const __nv_bfloat16* pBh = Bh + (size_t)(n0 + lr) * D_ + lce;
    const __nv_bfloat16* pBl = USE_BL ? (Bl + (size_t)(n0 + lr) * D_ + lce) : pBh;

#define ISSUE(kc, buf) do {                                                  \
    uint32_t _bb = smu + (buf) * BUF_B + sto;                                \
    const int _o = (kc) * KC_;                                               \
    CP16(_bb, pAh + _o);                 CP16(_bb + 16, pAh + _o + 8);       \
    CP16(_bb + TILE_B, pAl + _o);        CP16(_bb + TILE_B + 16, pAl + _o + 8); \
    CP16(_bb + 2 * TILE_B, pBh + _o);    CP16(_bb + 2 * TILE_B + 16, pBh + _o + 8); \
    if (USE_BL) {                                                            \
        CP16(_bb + 3 * TILE_B, pBl + _o);                                    \
        CP16(_bb + 3 * TILE_B + 16, pBl + _o + 8);                           \
    }                                                                        \
    CP_COMMIT(); } while (0)

    ISSUE(0, 0);

    const int arow = (lane & 7) + ((lane >> 3) & 1) * 8;
    const int acolb = (lane >> 4) * 16;
    const int brow = (lane & 7) + (lane >> 4) * 8;
    const int bcolb = ((lane >> 3) & 1) * 16;

    for (int kc = 0; kc < NKC_; ++kc) {
        CP_WAIT0();            // only chunk kc's group is in flight
        __syncthreads();       // buf kc&1 ready; all prior-iter reads complete
        const uint32_t bufb = smu + (kc & 1) * BUF_B;
        const uint32_t aA0 = bufb + (uint32_t)(wm * 32 + arow) * TROW_B + acolb;
        const uint32_t bB0 = bufb + 2 * TILE_B + (uint32_t)(wn * 64 + brow) * TROW_B + bcolb;
#pragma unroll
        for (int ks = 0; ks < 2; ++ks) {
            uint32_t ah[2][4], al[2][4], bh[4][4], bl[4][4];
#pragma unroll
            for (int mf = 0; mf < 2; ++mf) {
                ldsm_x4(ah[mf], aA0 + mf * 16 * TROW_B + ks * 32);
                ldsm_x4(al[mf], aA0 + TILE_B + mf * 16 * TROW_B + ks * 32);
            }
#pragma unroll
            for (int nfp = 0; nfp < 4; ++nfp) {
                ldsm_x4(bh[nfp], bB0 + nfp * 16 * TROW_B + ks * 32);
                if (USE_BL) ldsm_x4(bl[nfp], bB0 + TILE_B + nfp * 16 * TROW_B + ks * 32);
            }
            if (ks == 0 && kc + 1 < NKC_) ISSUE(kc + 1, (kc + 1) & 1);
#pragma unroll
            for (int nfp = 0; nfp < 4; ++nfp)
#pragma unroll
                for (int hf = 0; hf < 2; ++hf) {
                    const int nf = nfp * 2 + hf;
                    const uint32_t b0h = bh[nfp][hf * 2], b1h = bh[nfp][hf * 2 + 1];
#pragma unroll
                    for (int mf = 0; mf < 2; ++mf) {
                        mma16816(acc[mf][nf], ah[mf][0], ah[mf][1], ah[mf][2], ah[mf][3], b0h, b1h);
                        mma16816(acc[mf][nf], al[mf][0], al[mf][1], al[mf][2], al[mf][3], b0h, b1h);
                        if (USE_BL)
                            mma16816(acc[mf][nf], ah[mf][0], ah[mf][1], ah[mf][2], ah[mf][3],
                                     bl[nfp][hf * 2], bl[nfp][hf * 2 + 1]);
                    }
                }
        }
    }
    __syncthreads();
#undef ISSUE
}

// ---------------------------------------------------------------------------
// Combined GEMM kernel: z=0 -> h GEMM (bf16x3, split store + src/dst logits);
//                       z=1 -> gate GEMM (bf16x2, store sigmoid(acc+Hb)).
// ---------------------------------------------------------------------------
__global__ __launch_bounds__(256, 2) void gemm_all_kernel(const float* __restrict__ wsrc,
                                                          const float* __restrict__ wdst,
                                                          const float* __restrict__ Hb) {
    extern __shared__ char sm[];
    const int m0 = blockIdx.y << 7;
    const int n0 = blockIdx.x << 7;
    float acc[2][8][4];
#pragma unroll
    for (int mf = 0; mf < 2; ++mf)
#pragma unroll
        for (int nf = 0; nf < 8; ++nf)
#pragma unroll
            for (int q = 0; q < 4; ++q) acc[mf][nf][q] = 0.f;

    const int warp = threadIdx.x >> 5, lane = threadIdx.x & 31;
    const int wm = warp & 3, wn = warp >> 2;
    const int g = lane >> 2, t = lane & 3;

    if (blockIdx.z == 0) {
        hmma_mainloop<true>(acc, g_fh, g_fl, g_w1h, g_w1l, m0, n0, sm);
        const int head = (n0 >> 6) + wn;
        float sd[2][2], dd[2][2];
#pragma unroll
        for (int mf = 0; mf < 2; ++mf) sd[mf][0] = sd[mf][1] = dd[mf][0] = dd[mf][1] = 0.f;
#pragma unroll
        for (int mf = 0; mf < 2; ++mf) {
            const int m = m0 + wm * 32 + mf * 16 + g;
            const int b = m >> 9, i = m & (N_ - 1);
            const int ba = b * A_ + head;
#pragma unroll
            for (int nf = 0; nf < 8; ++nf) {
                const int e = nf * 8 + 2 * t;
                __nv_bfloat16 h0, l0, h1, l1;
                split2(acc[mf][nf][0], h0, l0);
                split2(acc[mf][nf][1], h1, l1);
                *(__nv_bfloat162*)&g_hbh[((size_t)(ba * N_ + i)) * E_ + e] = __nv_bfloat162(h0, h1);
                *(__nv_bfloat162*)&g_hbl[((size_t)(ba * N_ + i)) * E_ + e] = __nv_bfloat162(l0, l1);
                split2(acc[mf][nf][2], h0, l0);
                split2(acc[mf][nf][3], h1, l1);
                *(__nv_bfloat162*)&g_hbh[((size_t)(ba * N_ + i + 8)) * E_ + e] = __nv_bfloat162(h0, h1);
                *(__nv_bfloat162*)&g_hbl[((size_t)(ba * N_ + i + 8)) * E_ + e] = __nv_bfloat162(l0, l1);
                float2 ws = *(const float2*)(wsrc + head * E_ + e);
                float2 wd = *(const float2*)(wdst + head * E_ + e);
                float t0 = tanhf(acc[mf][nf][0]), t1 = tanhf(acc[mf][nf][1]);
                float t2 = tanhf(acc[mf][nf][2]), t3 = tanhf(acc[mf][nf][3]);
                sd[mf][0] += t0 * ws.x + t1 * ws.y;
                sd[mf][1] += t2 * ws.x + t3 * ws.y;
                dd[mf][0] += t0 * wd.x + t1 * wd.y;
                dd[mf][1] += t2 * wd.x + t3 * wd.y;
            }
#pragma unroll
            for (int rh = 0; rh < 2; ++rh) {
                float s = sd[mf][rh], d = dd[mf][rh];
                s += __shfl_xor_sync(0xffffffffu, s, 1);
                s += __shfl_xor_sync(0xffffffffu, s, 2);
                d += __shfl_xor_sync(0xffffffffu, d, 1);
                d += __shfl_xor_sync(0xffffffffu, d, 2);
                if (t == 0) {
                    g_src[ba * N_ + i + rh * 8] = s;
                    g_dst[ba * N_ + i + rh * 8] = d;
                }
            }
        }
    } else {
        hmma_mainloop<false>(acc, g_fh, g_fl, g_w2h, g_w2h, m0, n0, sm);
#pragma unroll
        for (int mf = 0; mf < 2; ++mf)
#pragma unroll
            for (int nf = 0; nf < 8; ++nf) {
                const int m = m0 + wm * 32 + mf * 16 + g;
                const int n = n0 + wn * 64 + nf * 8 + 2 * t;
                float2 hb = *(const float2*)(Hb + n);
#pragma unroll
                for (int rr = 0; rr < 2; ++rr) {
                    const int mm = m + rr * 8;
                    float2 gv;
                    gv.x = 1.f / (1.f + __expf(-(acc[mf][nf][rr * 2 + 0] + hb.x)));
                    gv.y = 1.f / (1.f + __expf(-(acc[mf][nf][rr * 2 + 1] + hb.y)));
                    *(float2*)(g_gate + (size_t)mm * D_ + n) = gv;
                }
            }
    }
}

// ---------------------------------------------------------------------------
// Attention (HMMA, i-tile 64, 3 CTAs/SM) + fused highway blend epilogue:
// out = gate*elu(attn_out) + (1-gate)*feat   (written directly to d_out)
// ---------------------------------------------------------------------------
#define IT_ 64
#define HC_ROWB 144
#define HC_BUF_B (64 * HC_ROWB)          // 9216
#define P_ROWB 144
#define OFF_HCH 0
#define OFF_HCL 18432
#define OFF_PBH 36864
#define OFF_PBL 46080
#define OFF_SRC 55296
#define OFF_DST 55552
#define OFF_MS  57600
#define OFF_SUM 61696
#define ATT_SMEM_B 61952

__global__ __launch_bounds__(256, 3) void attn_kernel(const void* __restrict__ adjv,
                                                      const float* __restrict__ bbias,
                                                      const float* __restrict__ feat,
                                                      float* __restrict__ out) {
    extern __shared__ char sm[];
    const uint32_t smu = smem_u32(sm);
    char* Pbh = sm + OFF_PBH;
    char* Pbl = sm + OFF_PBL;
    float* s_src = (float*)(sm + OFF_SRC);
    float* s_dst = (float*)(sm + OFF_DST);
    float* s_sum = (float*)(sm + OFF_SUM);
    unsigned short* Ms = (unsigned short*)(sm + OFF_MS);   // [32 jwords][64 rows]

    const int tid = threadIdx.x;
    const int lane = tid & 31, warp = tid >> 5;
    const int b = blockIdx.z, a = blockIdx.y, it = blockIdx.x;
    const int ba = b * A_ + a;
    const int i0 = it * IT_;

    const __nv_bfloat16* srcH = g_hbh + (size_t)ba * N_ * E_;
    const __nv_bfloat16* srcL = g_hbl + (size_t)ba * N_ * E_;

#define ISSUE_H(jc, buf) do {                                                \
    const int _j0 = (jc) * 64;                                               \
    _Pragma("unroll")                                                        \
    for (int _c = 0; _c < 2; ++_c) {                                         \
        const int _idx = tid * 2 + _c;                                       \
        const int _jr = _idx >> 3, _q = _idx & 7;                            \
        const uint32_t _dst = smu + OFF_HCH + (buf) * HC_BUF_B + _jr * HC_ROWB + _q * 16; \
        CP16(_dst, srcH + (size_t)(_j0 + _jr) * E_ + _q * 8);                \
        CP16(_dst + (OFF_HCL - OFF_HCH), srcL + (size_t)(_j0 + _jr) * E_ + _q * 8); \
    }                                                                        \
    CP_COMMIT(); } while (0)

    // ---- Phase A ----
    ISSUE_H(0, 0);
    if (tid < IT_) s_src[tid] = g_src[ba * N_ + i0 + tid];
    s_dst[tid] = g_dst[ba * N_ + tid];
    s_dst[tid + 256] = g_dst[ba * N_ + tid + 256];
    __syncthreads();

    // ---- Phase B: mask bits ----
    const int adj_int = g_adj_int;
    for (int rr = warp; rr < IT_; rr += 8) {
        const size_t rowoff = (size_t)(b * N_ + i0 + rr) * N_;
        unsigned mbits = 0;
        if (adj_int) {
            const uint4* ap = (const uint4*)((const int*)adjv + rowoff + lane * 16);
#pragma unroll
            for (int q = 0; q < 4; ++q) {
                uint4 w = ap[q];
                mbits |= (w.x ? 1u : 0u) << (q * 4 + 0);
                mbits |= (w.y ? 1u : 0u) << (q * 4 + 1);
                mbits |= (w.z ? 1u : 0u) << (q * 4 + 2);
                mbits |= (w.w ? 1u : 0u) << (q * 4 + 3);
            }
        } else {
            uint4 w = *(const uint4*)((const uint8_t*)adjv + rowoff + lane * 16);
            unsigned ws[4] = {w.x, w.y, w.z, w.w};
#pragma unroll
            for (int q = 0; q < 4; ++q)
#pragma unroll
                for (int bq = 0; bq < 4; ++bq)
                    mbits |= (((ws[q] >> (8 * bq)) & 0xffu) ? 1u : 0u) << (q * 4 + bq);
        }
        Ms[lane * IT_ + rr] = (unsigned short)mbits;
    }
    __syncthreads();

    // ---- Phase C ----
    const int wm = warp & 1, wn = warp >> 1;
    const int r = tid >> 2, jseg = (tid & 3) * 16;
    const float srcv = s_src[r];

    const int arow = (lane & 7) + ((lane >> 3) & 1) * 8;
    const int acolb = (lane >> 4) * 16;
    const uint32_t aP0 = smu + OFF_PBH + (uint32_t)(wm * 32 + arow) * P_ROWB + acolb;
    const int jrow = lane & 15;
    const int ecolb = (lane >> 4) * 16;
    const uint32_t bH0 = smu + OFF_HCH + (uint32_t)jrow * HC_ROWB + (wn * 16) * 2 + ecolb;

    float acc[2][2][4];
#pragma unroll
    for (int mf = 0; mf < 2; ++mf)
#pragma unroll
        for (int nf = 0; nf < 2; ++nf)
#pragma unroll
            for (int q = 0; q < 4; ++q) acc[mf][nf][q] = 0.f;

    float psum = 0.f;

    for (int jc = 0; jc < 8; ++jc) {
        {
            const int jb = jc * 64 + jseg;
            uint32_t mbits = Ms[(jb >> 4) * IT_ + r];
#pragma unroll
            for (int q = 0; q < 16; q += 4) {
                float4 dv = *(const float4*)&s_dst[jb + q];
                float p[4];
#pragma unroll
                for (int e = 0; e < 4; ++e) {
                    float v = srcv + (&dv.x)[e];
                    v = v >= 0.f ? v : 0.2f * v;
                    p[e] = ((mbits >> (q + e)) & 1u) ? __expf(v) : 0.f;
                    psum += p[e];
                }
                __nv_bfloat16 h0, l0, h1, l1;
                split2(p[0], h0, l0); split2(p[1], h1, l1);
                *(__nv_bfloat162*)(Pbh + r * P_ROWB + (jseg + q) * 2) = __nv_bfloat162(h0, h1);
                *(__nv_bfloat162*)(Pbl + r * P_ROWB + (jseg + q) * 2) = __nv_bfloat162(l0, l1);
                split2(p[2], h0, l0); split2(p[3], h1, l1);
                *(__nv_bfloat162*)(Pbh + r * P_ROWB + (jseg + q + 2) * 2) = __nv_bfloat162(h0, h1);
                *(__nv_bfloat162*)(Pbl + r * P_ROWB + (jseg + q + 2) * 2) = __nv_bfloat162(l0, l1);
            }
        }
        if (jc + 1 < 8) { ISSUE_H(jc + 1, (jc + 1) & 1); CP_WAIT1(); }
        else            { CP_WAIT0(); }
        __syncthreads();

        const uint32_t bbuf = bH0 + (jc & 1) * HC_BUF_B;
#pragma unroll
        for (int ks = 0; ks < 4; ++ks) {
            uint32_t ah[2][4], al[2][4], bh[4], bl[4];
#pragma unroll
            for (int mf = 0; mf < 2; ++mf) {
                ldsm_x4(ah[mf], aP0 + mf * 16 * P_ROWB + ks * 32);
                ldsm_x4(al[mf], aP0 + (OFF_PBL - OFF_PBH) + mf * 16 * P_ROWB + ks * 32);
            }
            const uint32_t bbase = bbuf + (uint32_t)(ks * 16) * HC_ROWB;
            ldsm_x4_t(bh, bbase);
            ldsm_x4_t(bl, bbase + (OFF_HCL - OFF_HCH));
#pragma unroll
            for (int nf = 0; nf < 2; ++nf) {
                const uint32_t b0h = bh[nf * 2], b1h = bh[nf * 2 + 1];
                const uint32_t b0l = bl[nf * 2], b1l = bl[nf * 2 + 1];
#pragma unroll
                for (int mf = 0; mf < 2; ++mf) {
                    mma16816(acc[mf][nf], ah[mf][0], ah[mf][1], ah[mf][2], ah[mf][3], b0h, b1h);
                    mma16816(acc[mf][nf], al[mf][0], al[mf][1], al[mf][2], al[mf][3], b0h, b1h);
                    mma16816(acc[mf][nf], ah[mf][0], ah[mf][1], ah[mf][2], ah[mf][3], b0l, b1l);
                }
            }
        }
        __syncthreads();
    }
#undef ISSUE_H

    // row-sum: quad-reduce and publish
    psum += __shfl_xor_sync(0xffffffffu, psum, 1);
    psum += __shfl_xor_sync(0xffffffffu, psum, 2);
    if ((tid & 3) == 0) s_sum[r] = psum;
    __syncthreads();

    // ---- epilogue: normalize + bias + elu + highway blend -> d_out ----
    const int g = lane >> 2, t = lane & 3;
#pragma unroll
    for (int mf = 0; mf < 2; ++mf) {
        const int rl = wm * 32 + mf * 16 + g;
        const float inv0 = __fdividef(1.f, s_sum[rl]);
        const float inv1 = __fdividef(1.f, s_sum[rl + 8]);
#pragma unroll
        for (int nf = 0; nf < 2; ++nf) {
            const int col = wn * 16 + nf * 8 + 2 * t;
            const int n = a * E_ + col;
            float2 bias = *(const float2*)(bbias + col);
#pragma unroll
            for (int rr = 0; rr < 2; ++rr) {
                const int row = i0 + rl + rr * 8;
                const size_t off = (size_t)(b * N_ + row) * D_ + n;
                const float inv = rr ? inv1 : inv0;
                float2 gv = *(const float2*)(g_gate + off);
                float2 fv = *(const float2*)(feat + off);
                float a0 = fmaf(acc[mf][nf][rr * 2 + 0], inv, bias.x);
                float a1 = fmaf(acc[mf][nf][rr * 2 + 1], inv, bias.y);
                float fo0 = a0 > 0.f ? a0 : (__expf(a0) - 1.f);
                float fo1 = a1 > 0.f ? a1 : (__expf(a1) - 1.f);
                float2 ov;
                ov.x = gv.x * fo0 + (1.f - gv.x) * fv.x;
                ov.y = gv.y * fo1 + (1.f - gv.y) * fv.y;
                *(float2*)(out + off) = ov;
            }
        }
    }
}

// ---------------------------------------------------------------------------
extern "C" void kernel_launch(void* const* d_in, const int* in_sizes, int n_in,
                              void* d_out, int out_size) {
    const float* feat = (const float*)d_in[0];
    const void* adj = d_in[1];
    const float* W = (const float*)d_in[2];
    const float* bbias = (const float*)d_in[3];
    const float* wsrc = (const float*)d_in[4];
    const float* wdst = (const float*)d_in[5];
    const float* Hw = (const float*)d_in[6];
    const float* Hb = (const float*)d_in[7];
    float* out = (float*)d_out;

    prep_kernel<<<PREP_GRID, 256>>>(feat, W, Hw, (const int*)adj);

    cudaFuncSetAttribute(gemm_all_kernel, cudaFuncAttributeMaxDynamicSharedMemorySize, GEMM_SMEM);
    cudaFuncSetAttribute(attn_kernel, cudaFuncAttributeMaxDynamicSharedMemorySize, ATT_SMEM_B);

    gemm_all_kernel<<<dim3(D_ / 128, M_ / 128, 2), 256, GEMM_SMEM>>>(wsrc, wdst, Hb);

    attn_kernel<<<dim3(N_ / IT_, A_, B_), 256, ATT_SMEM_B>>>(adj, bbias, feat, out);
}